// round 2
// baseline (speedup 1.0000x reference)
#include <cuda_runtime.h>

// Problem constants (fixed by the reference)
#define NN 50000
#define NE 800000
#define HEADS 2
#define OF 128           // out feats
#define IF 128           // in feats
#define NHO (NN*HEADS*OF)
#define NH  (NN*HEADS)

// ---------------- scratch (device globals; no runtime alloc) ----------------
__device__ float    g_ft[NHO];          // [n][h][o] projected features  (51.2MB)
__device__ float    g_el[NH];           // [n][h]
__device__ float    g_er[NH];           // [n][h]
__device__ float    g_ee[NE*HEADS];     // per-edge e values
__device__ unsigned g_emax[NH];         // ordered-uint encoded max
__device__ float    g_denom[NH];
__device__ int      g_deg[NN];
__device__ int      g_off[NN+1];
__device__ int      g_cnt[NN];
__device__ int      g_ssrc[NE];         // dst-sorted src ids
__device__ float    g_see[NE*HEADS];    // dst-sorted exp values
__device__ float    g_Wt[HEADS*IF*OF];  // W transposed: [h][i][o]

// ordered-uint encoding for float atomicMax
__device__ __forceinline__ unsigned fenc(float f) {
    unsigned u = __float_as_uint(f);
    return (u & 0x80000000u) ? ~u : (u | 0x80000000u);
}
__device__ __forceinline__ float fdec(unsigned u) {
    return (u & 0x80000000u) ? __uint_as_float(u & 0x7FFFFFFFu)
                             : __uint_as_float(~u);
}

// ---------------- init ----------------
__global__ void k_init() {
    int i = blockIdx.x * blockDim.x + threadIdx.x;
    if (i < NH) { g_emax[i] = 0u; g_denom[i] = 0.0f; }
    if (i < NN) { g_deg[i] = 0; g_cnt[i] = 0; }
}

// ---------------- W transpose: Wt[h][i][o] = W[h][o][i] ----------------
__global__ void k_trans(const float* __restrict__ W) {
    int i = blockIdx.x * blockDim.x + threadIdx.x;   // < 2*128*128
    int h = i >> 14;
    int r = i & 16383;
    int o = r >> 7;
    int ii = r & 127;
    g_Wt[(h << 14) + (ii << 7) + o] = W[i];
}

// ---------------- projection GEMM + el/er ----------------
// 128 threads. Thread map: ng = t>>6 (node half: 8 nodes), h = (t&63)>>5,
// q = t&31 (float4 column within head; 32*4 = 128 = OF exactly).
// Threads sharing (ng,h) form exactly one warp -> el/er are warp reductions.
#define NT 16
__global__ void __launch_bounds__(128) k_gemm(
    const float* __restrict__ feat,
    const float* __restrict__ attn_l,
    const float* __restrict__ attn_r)
{
    __shared__ float sfeat[NT * IF];

    int t = threadIdx.x;
    int n0 = blockIdx.x * NT;

    // load 16x128 feat tile (512 float4)
    {
        const float4* fsrc = (const float4*)(feat + (size_t)n0 * IF);
        float4* fdst = (float4*)sfeat;
#pragma unroll
        for (int k = 0; k < 4; k++) fdst[t + k * 128] = fsrc[t + k * 128];
    }
    __syncthreads();

    int ng  = t >> 6;          // 0/1: which 8-node group
    int col = t & 63;
    int h   = col >> 5;        // head
    int q   = col & 31;        // float4 column (o = q*4 .. q*4+3)

    float acc[8][4];
#pragma unroll
    for (int nn = 0; nn < 8; nn++) { acc[nn][0]=0.f; acc[nn][1]=0.f; acc[nn][2]=0.f; acc[nn][3]=0.f; }

    const float4* wp = (const float4*)g_Wt + (h << 12);   // 4096 float4 per head
    const float*  fb = sfeat + ng * 8 * IF;
#pragma unroll 4
    for (int i = 0; i < IF; i++) {
        float4 w = __ldg(&wp[i * 32 + q]);
#pragma unroll
        for (int nn = 0; nn < 8; nn++) {
            float f = fb[nn * IF + i];
            acc[nn][0] += w.x * f;
            acc[nn][1] += w.y * f;
            acc[nn][2] += w.z * f;
            acc[nn][3] += w.w * f;
        }
    }

    // write ft: g_ft[node][h][o]
#pragma unroll
    for (int nn = 0; nn < 8; nn++) {
        int node = n0 + ng * 8 + nn;
        ((float4*)g_ft)[(size_t)node * 64 + h * 32 + q] =
            make_float4(acc[nn][0], acc[nn][1], acc[nn][2], acc[nn][3]);
    }

    // el/er: each (ng,h) group is one warp -> pure shuffle reduction
    float4 al = __ldg(&((const float4*)attn_l)[h * 32 + q]);
    float4 ar = __ldg(&((const float4*)attn_r)[h * 32 + q]);
    int lane = t & 31;
#pragma unroll
    for (int nn = 0; nn < 8; nn++) {
        float pl = acc[nn][0]*al.x + acc[nn][1]*al.y + acc[nn][2]*al.z + acc[nn][3]*al.w;
        float pr = acc[nn][0]*ar.x + acc[nn][1]*ar.y + acc[nn][2]*ar.z + acc[nn][3]*ar.w;
#pragma unroll
        for (int s = 16; s >= 1; s >>= 1) {
            pl += __shfl_xor_sync(0xffffffffu, pl, s);
            pr += __shfl_xor_sync(0xffffffffu, pr, s);
        }
        if (lane == 0) {
            int node = n0 + ng * 8 + nn;
            g_el[node * 2 + h] = pl;
            g_er[node * 2 + h] = pr;
        }
    }
}

// ---------------- edge pass 1: e = leaky(el[s]+er[d]+ew), emax, degree ----------------
__global__ void k_edge1(const float* __restrict__ e_w,
                        const int* __restrict__ src,
                        const int* __restrict__ dst,
                        const float* __restrict__ attn_ew)
{
    int e = blockIdx.x * blockDim.x + threadIdx.x;
    if (e >= NE) return;
    int s = src[e], d = dst[e];
    float2 ew = ((const float2*)e_w)[e];
    float2 a = ((const float2*)g_el)[s];
    float2 b = ((const float2*)g_er)[d];
    float w00 = __ldg(&attn_ew[0]), w01 = __ldg(&attn_ew[1]);
    float w10 = __ldg(&attn_ew[2]), w11 = __ldg(&attn_ew[3]);

    float v0 = a.x + b.x + ew.x * w00 + ew.y * w01;
    float v1 = a.y + b.y + ew.x * w10 + ew.y * w11;
    v0 = v0 > 0.f ? v0 : 0.2f * v0;
    v1 = v1 > 0.f ? v1 : 0.2f * v1;
    ((float2*)g_ee)[e] = make_float2(v0, v1);
    atomicMax(&g_emax[d * 2 + 0], fenc(v0));
    atomicMax(&g_emax[d * 2 + 1], fenc(v1));
    atomicAdd(&g_deg[d], 1);
}

// ---------------- exclusive scan of degrees (single block) ----------------
__global__ void k_scan(int n) {
    __shared__ int wsum[32];
    __shared__ int s_carry, s_tot;
    int t = threadIdx.x, lane = t & 31, w = t >> 5;
    if (t == 0) s_carry = 0;
    __syncthreads();
    for (int base = 0; base < n; base += 1024) {
        int i = base + t;
        int x = (i < n) ? g_deg[i] : 0;
        int incl = x;
#pragma unroll
        for (int s = 1; s < 32; s <<= 1) {
            int v = __shfl_up_sync(0xffffffffu, incl, s);
            if (lane >= s) incl += v;
        }
        if (lane == 31) wsum[w] = incl;
        __syncthreads();
        if (w == 0) {
            int ws = wsum[lane];
            int wi = ws;
#pragma unroll
            for (int s = 1; s < 32; s <<= 1) {
                int v = __shfl_up_sync(0xffffffffu, wi, s);
                if (lane >= s) wi += v;
            }
            wsum[lane] = wi - ws;          // exclusive warp offset
            if (lane == 31) s_tot = wi;    // block total
        }
        __syncthreads();
        if (i < n) g_off[i] = s_carry + wsum[w] + incl - x;
        __syncthreads();
        if (t == 0) s_carry += s_tot;
        __syncthreads();
    }
    if (t == 0) g_off[n] = s_carry;
}

// ---------------- edge pass 2: counting-sort scatter + exp + denom ----------------
__global__ void k_edge2(const int* __restrict__ src,
                        const int* __restrict__ dst)
{
    int e = blockIdx.x * blockDim.x + threadIdx.x;
    if (e >= NE) return;
    int d = dst[e];
    int pos = atomicAdd(&g_cnt[d], 1);
    int idx = g_off[d] + pos;
    g_ssrc[idx] = src[e];
    float2 ev = ((const float2*)g_ee)[e];
    uint2 mk = ((const uint2*)g_emax)[d];
    float ee0 = __expf(ev.x - fdec(mk.x));
    float ee1 = __expf(ev.y - fdec(mk.y));
    atomicAdd(&g_denom[d * 2 + 0], ee0);
    atomicAdd(&g_denom[d * 2 + 1], ee1);
    ((float2*)g_see)[idx] = make_float2(ee0, ee1);
}

// ---------------- aggregation: one block per dst node ----------------
__global__ void __launch_bounds__(256) k_agg(const float* __restrict__ feat,
                                             float* __restrict__ out)
{
    __shared__ int   ssrc[128];
    __shared__ float sa[256];
    int d = blockIdx.x;
    int t = threadIdx.x;
    int h = t >> 7, o = t & 127;
    int beg = g_off[d], end = g_off[d + 1];
    float acc = 0.0f;

    for (int base = beg; base < end; base += 128) {
        int n = min(128, end - base);
        if (t < n) ssrc[t] = g_ssrc[base + t];
        if (t < 2 * n) sa[t] = g_see[2 * base + t];
        __syncthreads();
        int j = 0;
        for (; j + 4 <= n; j += 4) {
            int s0 = ssrc[j], s1 = ssrc[j + 1], s2 = ssrc[j + 2], s3 = ssrc[j + 3];
            float f0 = __ldg(&g_ft[(size_t)s0 * 256 + t]);
            float f1 = __ldg(&g_ft[(size_t)s1 * 256 + t]);
            float f2 = __ldg(&g_ft[(size_t)s2 * 256 + t]);
            float f3 = __ldg(&g_ft[(size_t)s3 * 256 + t]);
            acc += f0 * sa[2 * j + h];
            acc += f1 * sa[2 * j + 2 + h];
            acc += f2 * sa[2 * j + 4 + h];
            acc += f3 * sa[2 * j + 6 + h];
        }
        for (; j < n; j++)
            acc += __ldg(&g_ft[(size_t)ssrc[j] * 256 + t]) * sa[2 * j + h];
        __syncthreads();
    }

    float den = g_denom[d * 2 + h];
    float inv = den > 0.f ? 1.0f / den : 0.0f;
    float r = acc * inv + feat[(size_t)d * 128 + o];
    out[(size_t)d * 256 + t] = r > 0.f ? r : (__expf(r) - 1.0f);
}

// ---------------- launcher ----------------
extern "C" void kernel_launch(void* const* d_in, const int* in_sizes, int n_in,
                              void* d_out, int out_size)
{
    const float* feat    = (const float*)d_in[0];
    const float* e_w     = (const float*)d_in[1];
    const int*   src     = (const int*)  d_in[2];
    const int*   dst     = (const int*)  d_in[3];
    const float* W       = (const float*)d_in[4];
    const float* attn_l  = (const float*)d_in[5];
    const float* attn_r  = (const float*)d_in[6];
    const float* attn_ew = (const float*)d_in[7];
    float* out = (float*)d_out;

    k_init<<<(NH + 255) / 256, 256>>>();
    k_trans<<<(HEADS * IF * OF) / 256, 256>>>(W);
    k_gemm<<<NN / NT, 128>>>(feat, attn_l, attn_r);
    k_edge1<<<(NE + 255) / 256, 256>>>(e_w, src, dst, attn_ew);
    k_scan<<<1, 1024>>>(NN);
    k_edge2<<<(NE + 255) / 256, 256>>>(src, dst);
    k_agg<<<NN, 256>>>(feat, out);
}

// round 3
// speedup vs baseline: 1.1110x; 1.1110x over previous
#include <cuda_runtime.h>

// Problem constants (fixed by the reference)
#define NN 50000
#define NE 800000
#define HEADS 2
#define OF 128           // out feats
#define IF 128           // in feats
#define NHO (NN*HEADS*OF)
#define NH  (NN*HEADS)

// ---------------- scratch (device globals; no runtime alloc) ----------------
__device__ float    g_ft[NHO];          // [n][h][o] projected features  (51.2MB)
__device__ float    g_el[NH];           // [n][h]
__device__ float    g_er[NH];           // [n][h]
__device__ float    g_ee[NE*HEADS];     // per-edge exp values
__device__ float    g_denom[NH];
__device__ int      g_deg[NN];
__device__ int      g_off[NN+4];
__device__ int      g_cnt[NN];
__device__ int      g_ssrc[NE];         // dst-sorted src ids
__device__ float    g_see[NE*HEADS];    // dst-sorted exp values
__device__ float    g_Wt[HEADS*IF*OF];  // W transposed: [h][i][o]

// ---------------- f32x2 packed helpers ----------------
__device__ __forceinline__ unsigned long long dup2(float x) {
    unsigned u = __float_as_uint(x);
    unsigned long long d;
    asm("mov.b64 %0, {%1, %1};" : "=l"(d) : "r"(u));
    return d;
}
#define FMA2(d, a, b) asm("fma.rn.f32x2 %0, %1, %2, %0;" : "+l"(d) : "l"(a), "l"(b))
__device__ __forceinline__ void unpack2(unsigned long long v, float& lo, float& hi) {
    unsigned a, b;
    asm("mov.b64 {%0, %1}, %2;" : "=r"(a), "=r"(b) : "l"(v));
    lo = __uint_as_float(a); hi = __uint_as_float(b);
}

// ---------------- setup: zero accumulators + transpose W ----------------
__global__ void k_setup(const float* __restrict__ W) {
    int i = blockIdx.x * blockDim.x + threadIdx.x;
    if (i < NH) g_denom[i] = 0.0f;
    if (i < NN) { g_deg[i] = 0; g_cnt[i] = 0; }
    if (i < HEADS * IF * OF) {
        int h = i >> 14;
        int r = i & 16383;
        int o = r >> 7;
        int ii = r & 127;
        g_Wt[(h << 14) + (ii << 7) + o] = W[i];
    }
}

// ---------------- projection GEMM (f32x2 packed) + el/er ----------------
// 128 threads. ng = t>>6 (8-node group = 4 node pairs), h = (t&63)>>5,
// q = t&31 (float4 column within head). Each warp = fixed (ng,h).
#define NT 16
#define SFP 18   // padded smem row stride (floats); even -> 8B-aligned pairs
__global__ void __launch_bounds__(128) k_gemm(
    const float* __restrict__ feat,
    const float* __restrict__ attn_l,
    const float* __restrict__ attn_r)
{
    __shared__ float sft[IF * SFP];   // transposed tile: [i][node], 9216 B

    int t = threadIdx.x;
    int n0 = blockIdx.x * NT;

    // load 16x128 feat tile and store transposed: sft[c][node]
    {
        const float4* fsrc = (const float4*)(feat + (size_t)n0 * IF);
#pragma unroll
        for (int k = 0; k < 4; k++) {
            float4 v = fsrc[t + k * 128];
            int g = t + k * 128;
            int node = g >> 5;
            int c4 = g & 31;
            sft[(4 * c4 + 0) * SFP + node] = v.x;
            sft[(4 * c4 + 1) * SFP + node] = v.y;
            sft[(4 * c4 + 2) * SFP + node] = v.z;
            sft[(4 * c4 + 3) * SFP + node] = v.w;
        }
    }
    __syncthreads();

    int ng  = t >> 6;          // 0/1: which 8-node group
    int col = t & 63;
    int h   = col >> 5;        // head
    int q   = col & 31;        // float4 column (o = q*4 .. q*4+3)

    unsigned long long acc[4][4];   // [node pair][o component]
#pragma unroll
    for (int p = 0; p < 4; p++)
#pragma unroll
        for (int c = 0; c < 4; c++) acc[p][c] = 0ull;

    const float4* wp = (const float4*)g_Wt + (h << 12);
    const float*  fb = sft + ng * 8;
#pragma unroll 4
    for (int i = 0; i < IF; i++) {
        float4 w = wp[i * 32 + q];
        unsigned long long wx = dup2(w.x), wy = dup2(w.y),
                           wz = dup2(w.z), ww = dup2(w.w);
        const float* row = fb + i * SFP;
#pragma unroll
        for (int p = 0; p < 4; p++) {
            unsigned long long f = *(const unsigned long long*)(row + 2 * p);
            FMA2(acc[p][0], f, wx);
            FMA2(acc[p][1], f, wy);
            FMA2(acc[p][2], f, wz);
            FMA2(acc[p][3], f, ww);
        }
    }

    // epilogue: unpack, store ft, reduce el/er
    float4 al = ((const float4*)attn_l)[h * 32 + q];
    float4 ar = ((const float4*)attn_r)[h * 32 + q];
    int lane = t & 31;
#pragma unroll
    for (int p = 0; p < 4; p++) {
        float a0x, a1x, a0y, a1y, a0z, a1z, a0w, a1w;
        unpack2(acc[p][0], a0x, a1x);
        unpack2(acc[p][1], a0y, a1y);
        unpack2(acc[p][2], a0z, a1z);
        unpack2(acc[p][3], a0w, a1w);
        int node0 = n0 + ng * 8 + 2 * p;
        ((float4*)g_ft)[(size_t)node0 * 64 + h * 32 + q] = make_float4(a0x, a0y, a0z, a0w);
        ((float4*)g_ft)[(size_t)(node0 + 1) * 64 + h * 32 + q] = make_float4(a1x, a1y, a1z, a1w);

        float pl0 = a0x*al.x + a0y*al.y + a0z*al.z + a0w*al.w;
        float pr0 = a0x*ar.x + a0y*ar.y + a0z*ar.z + a0w*ar.w;
        float pl1 = a1x*al.x + a1y*al.y + a1z*al.z + a1w*al.w;
        float pr1 = a1x*ar.x + a1y*ar.y + a1z*ar.z + a1w*ar.w;
#pragma unroll
        for (int s = 16; s >= 1; s >>= 1) {
            pl0 += __shfl_xor_sync(0xffffffffu, pl0, s);
            pr0 += __shfl_xor_sync(0xffffffffu, pr0, s);
            pl1 += __shfl_xor_sync(0xffffffffu, pl1, s);
            pr1 += __shfl_xor_sync(0xffffffffu, pr1, s);
        }
        if (lane == 0) {
            g_el[node0 * 2 + h] = pl0;
            g_er[node0 * 2 + h] = pr0;
            g_el[(node0 + 1) * 2 + h] = pl1;
            g_er[(node0 + 1) * 2 + h] = pr1;
        }
    }
}

// ---------------- edge pass 1: ee = exp(leaky(el[s]+er[d]+ew)), denom, deg ----------------
// (softmax is shift-invariant; |e| is O(10) so exp is fp32-safe without max-sub)
__global__ void k_edge1(const float* __restrict__ e_w,
                        const int* __restrict__ src,
                        const int* __restrict__ dst,
                        const float* __restrict__ attn_ew)
{
    int e = blockIdx.x * blockDim.x + threadIdx.x;
    if (e >= NE) return;
    int s = src[e], d = dst[e];
    float2 ew = ((const float2*)e_w)[e];
    float2 a = ((const float2*)g_el)[s];
    float2 b = ((const float2*)g_er)[d];
    float w00 = __ldg(&attn_ew[0]), w01 = __ldg(&attn_ew[1]);
    float w10 = __ldg(&attn_ew[2]), w11 = __ldg(&attn_ew[3]);

    float v0 = a.x + b.x + ew.x * w00 + ew.y * w01;
    float v1 = a.y + b.y + ew.x * w10 + ew.y * w11;
    v0 = v0 > 0.f ? v0 : 0.2f * v0;
    v1 = v1 > 0.f ? v1 : 0.2f * v1;
    float ee0 = __expf(v0);
    float ee1 = __expf(v1);
    ((float2*)g_ee)[e] = make_float2(ee0, ee1);
    atomicAdd(&g_denom[d * 2 + 0], ee0);
    atomicAdd(&g_denom[d * 2 + 1], ee1);
    atomicAdd(&g_deg[d], 1);
}

// ---------------- exclusive scan of degrees (single block, 4 elems/thread) ----------------
__global__ void k_scan() {
    __shared__ int wsum[32];
    __shared__ int s_carry, s_tot;
    const int n4 = NN / 4;   // 12500
    int t = threadIdx.x, lane = t & 31, w = t >> 5;
    if (t == 0) s_carry = 0;
    __syncthreads();
    for (int base = 0; base < n4; base += 1024) {
        int i = base + t;
        int4 x = (i < n4) ? ((const int4*)g_deg)[i] : make_int4(0, 0, 0, 0);
        int s0 = x.x, s1 = s0 + x.y, s2 = s1 + x.z, s3 = s2 + x.w;
        int incl = s3;
#pragma unroll
        for (int s = 1; s < 32; s <<= 1) {
            int v = __shfl_up_sync(0xffffffffu, incl, s);
            if (lane >= s) incl += v;
        }
        if (lane == 31) wsum[w] = incl;
        __syncthreads();
        if (w == 0) {
            int ws = wsum[lane];
            int wi = ws;
#pragma unroll
            for (int s = 1; s < 32; s <<= 1) {
                int v = __shfl_up_sync(0xffffffffu, wi, s);
                if (lane >= s) wi += v;
            }
            wsum[lane] = wi - ws;          // exclusive warp offset
            if (lane == 31) s_tot = wi;    // block total
        }
        __syncthreads();
        if (i < n4) {
            int ex = s_carry + wsum[w] + incl - s3;
            ((int4*)g_off)[i] = make_int4(ex, ex + s0, ex + s1, ex + s2);
        }
        __syncthreads();
        if (t == 0) s_carry += s_tot;
        __syncthreads();
    }
    if (t == 0) g_off[NN] = s_carry;
}

// ---------------- edge pass 2: counting-sort scatter ----------------
__global__ void k_edge2(const int* __restrict__ src,
                        const int* __restrict__ dst)
{
    int e = blockIdx.x * blockDim.x + threadIdx.x;
    if (e >= NE) return;
    int d = dst[e];
    int pos = atomicAdd(&g_cnt[d], 1);
    int idx = g_off[d] + pos;
    g_ssrc[idx] = src[e];
    ((float2*)g_see)[idx] = ((const float2*)g_ee)[e];
}

// ---------------- aggregation: one block per dst node ----------------
__global__ void __launch_bounds__(256) k_agg(const float* __restrict__ feat,
                                             float* __restrict__ out)
{
    __shared__ int   ssrc[128];
    __shared__ float sa[256];
    int d = blockIdx.x;
    int t = threadIdx.x;
    int h = t >> 7, o = t & 127;
    int beg = g_off[d], end = g_off[d + 1];
    float acc = 0.0f;

    for (int base = beg; base < end; base += 128) {
        int n = min(128, end - base);
        if (t < n) ssrc[t] = g_ssrc[base + t];
        if (t < 2 * n) sa[t] = g_see[2 * base + t];
        __syncthreads();
        int j = 0;
        for (; j + 4 <= n; j += 4) {
            int s0 = ssrc[j], s1 = ssrc[j + 1], s2 = ssrc[j + 2], s3 = ssrc[j + 3];
            float f0 = __ldg(&g_ft[(size_t)s0 * 256 + t]);
            float f1 = __ldg(&g_ft[(size_t)s1 * 256 + t]);
            float f2 = __ldg(&g_ft[(size_t)s2 * 256 + t]);
            float f3 = __ldg(&g_ft[(size_t)s3 * 256 + t]);
            acc += f0 * sa[2 * j + h];
            acc += f1 * sa[2 * j + 2 + h];
            acc += f2 * sa[2 * j + 4 + h];
            acc += f3 * sa[2 * j + 6 + h];
        }
        for (; j < n; j++)
            acc += __ldg(&g_ft[(size_t)ssrc[j] * 256 + t]) * sa[2 * j + h];
        __syncthreads();
    }

    float den = g_denom[d * 2 + h];
    float inv = den > 0.f ? 1.0f / den : 0.0f;
    float r = acc * inv + feat[(size_t)d * 128 + o];
    out[(size_t)d * 256 + t] = r > 0.f ? r : (__expf(r) - 1.0f);
}

// ---------------- launcher ----------------
extern "C" void kernel_launch(void* const* d_in, const int* in_sizes, int n_in,
                              void* d_out, int out_size)
{
    const float* feat    = (const float*)d_in[0];
    const float* e_w     = (const float*)d_in[1];
    const int*   src     = (const int*)  d_in[2];
    const int*   dst     = (const int*)  d_in[3];
    const float* W       = (const float*)d_in[4];
    const float* attn_l  = (const float*)d_in[5];
    const float* attn_r  = (const float*)d_in[6];
    const float* attn_ew = (const float*)d_in[7];
    float* out = (float*)d_out;

    k_setup<<<(NH + 255) / 256, 256>>>(W);
    k_gemm<<<NN / NT, 128>>>(feat, attn_l, attn_r);
    k_edge1<<<(NE + 255) / 256, 256>>>(e_w, src, dst, attn_ew);
    k_scan<<<1, 1024>>>();
    k_edge2<<<(NE + 255) / 256, 256>>>(src, dst);
    k_agg<<<NN, 256>>>(feat, out);
}

// round 4
// speedup vs baseline: 1.5521x; 1.3970x over previous
#include <cuda_runtime.h>
#include <cuda_fp16.h>

// Problem constants (fixed by the reference)
#define NN 50000
#define NE 800000
#define HEADS 2
#define OF 128           // out feats
#define IF 128           // in feats
#define NHO (NN*HEADS*OF)
#define NH  (NN*HEADS)

// ---------------- scratch (device globals; no runtime alloc) ----------------
__device__ __half   g_fth[NHO];         // [n][h][o] projected features, fp16 (25.6MB)
__device__ float    g_el[NH];           // [n][h]
__device__ float    g_er[NH];           // [n][h]
__device__ float    g_ee[NE*HEADS];     // per-edge exp values
__device__ float    g_denom[NH];
__device__ int      g_deg[NN];
__device__ int      g_off[NN+4];
__device__ int      g_cnt[NN];
__device__ int      g_ssrc[NE];         // dst-sorted src ids
__device__ float    g_see[NE*HEADS];    // dst-sorted exp values
__device__ float    g_Wt[HEADS*IF*OF];  // W transposed: [h][i][o]
__device__ volatile long long g_binc[16]; // chained-scan carries (-1 = not ready)

// ---------------- f32x2 packed helpers ----------------
__device__ __forceinline__ unsigned long long dup2(float x) {
    unsigned u = __float_as_uint(x);
    unsigned long long d;
    asm("mov.b64 %0, {%1, %1};" : "=l"(d) : "r"(u));
    return d;
}
#define FMA2(d, a, b) asm("fma.rn.f32x2 %0, %1, %2, %0;" : "+l"(d) : "l"(a), "l"(b))
__device__ __forceinline__ void unpack2(unsigned long long v, float& lo, float& hi) {
    unsigned a, b;
    asm("mov.b64 {%0, %1}, %2;" : "=r"(a), "=r"(b) : "l"(v));
    lo = __uint_as_float(a); hi = __uint_as_float(b);
}

// ---------------- setup: zero accumulators + transpose W + reset scan flags ----------------
__global__ void k_setup(const float* __restrict__ W) {
    int i = blockIdx.x * blockDim.x + threadIdx.x;
    if (i < NH) g_denom[i] = 0.0f;
    if (i < NN) { g_deg[i] = 0; g_cnt[i] = 0; }
    if (i < 16) g_binc[i] = -1ll;
    if (i < HEADS * IF * OF) {
        int h = i >> 14;
        int r = i & 16383;
        int o = r >> 7;
        int ii = r & 127;
        g_Wt[(h << 14) + (ii << 7) + o] = W[i];
    }
}

// ---------------- projection GEMM (f32x2 packed) + el/er, fp16 ft out ----------------
#define NT 16
#define SFP 18   // padded smem row stride (floats); even -> 8B-aligned pairs
__global__ void __launch_bounds__(128) k_gemm(
    const float* __restrict__ feat,
    const float* __restrict__ attn_l,
    const float* __restrict__ attn_r)
{
    __shared__ float sft[IF * SFP];   // transposed tile: [i][node]

    int t = threadIdx.x;
    int n0 = blockIdx.x * NT;

    // load 16x128 feat tile and store transposed: sft[c][node]
    {
        const float4* fsrc = (const float4*)(feat + (size_t)n0 * IF);
#pragma unroll
        for (int k = 0; k < 4; k++) {
            float4 v = fsrc[t + k * 128];
            int g = t + k * 128;
            int node = g >> 5;
            int c4 = g & 31;
            sft[(4 * c4 + 0) * SFP + node] = v.x;
            sft[(4 * c4 + 1) * SFP + node] = v.y;
            sft[(4 * c4 + 2) * SFP + node] = v.z;
            sft[(4 * c4 + 3) * SFP + node] = v.w;
        }
    }
    __syncthreads();

    int ng  = t >> 6;          // 0/1: which 8-node group
    int col = t & 63;
    int h   = col >> 5;        // head
    int q   = col & 31;        // float4 column (o = q*4 .. q*4+3)

    unsigned long long acc[4][4];   // [node pair][o component]
#pragma unroll
    for (int p = 0; p < 4; p++)
#pragma unroll
        for (int c = 0; c < 4; c++) acc[p][c] = 0ull;

    const float4* wp = (const float4*)g_Wt + (h << 12);
    const float*  fb = sft + ng * 8;
#pragma unroll 4
    for (int i = 0; i < IF; i++) {
        float4 w = wp[i * 32 + q];
        unsigned long long wx = dup2(w.x), wy = dup2(w.y),
                           wz = dup2(w.z), ww = dup2(w.w);
        const float* row = fb + i * SFP;
#pragma unroll
        for (int p = 0; p < 4; p++) {
            unsigned long long f = *(const unsigned long long*)(row + 2 * p);
            FMA2(acc[p][0], f, wx);
            FMA2(acc[p][1], f, wy);
            FMA2(acc[p][2], f, wz);
            FMA2(acc[p][3], f, ww);
        }
    }

    // epilogue: unpack, store ft (fp16), reduce el/er (fp32)
    float4 al = ((const float4*)attn_l)[h * 32 + q];
    float4 ar = ((const float4*)attn_r)[h * 32 + q];
    int lane = t & 31;
#pragma unroll
    for (int p = 0; p < 4; p++) {
        float a0x, a1x, a0y, a1y, a0z, a1z, a0w, a1w;
        unpack2(acc[p][0], a0x, a1x);
        unpack2(acc[p][1], a0y, a1y);
        unpack2(acc[p][2], a0z, a1z);
        unpack2(acc[p][3], a0w, a1w);
        int node0 = n0 + ng * 8 + 2 * p;

        __half2 h0a = __floats2half2_rn(a0x, a0y);
        __half2 h0b = __floats2half2_rn(a0z, a0w);
        __half2 h1a = __floats2half2_rn(a1x, a1y);
        __half2 h1b = __floats2half2_rn(a1z, a1w);
        uint2 u0, u1;
        u0.x = *(unsigned*)&h0a; u0.y = *(unsigned*)&h0b;
        u1.x = *(unsigned*)&h1a; u1.y = *(unsigned*)&h1b;
        ((uint2*)g_fth)[(size_t)node0 * 64 + h * 32 + q] = u0;
        ((uint2*)g_fth)[(size_t)(node0 + 1) * 64 + h * 32 + q] = u1;

        float pl0 = a0x*al.x + a0y*al.y + a0z*al.z + a0w*al.w;
        float pr0 = a0x*ar.x + a0y*ar.y + a0z*ar.z + a0w*ar.w;
        float pl1 = a1x*al.x + a1y*al.y + a1z*al.z + a1w*al.w;
        float pr1 = a1x*ar.x + a1y*ar.y + a1z*ar.z + a1w*ar.w;
#pragma unroll
        for (int s = 16; s >= 1; s >>= 1) {
            pl0 += __shfl_xor_sync(0xffffffffu, pl0, s);
            pr0 += __shfl_xor_sync(0xffffffffu, pr0, s);
            pl1 += __shfl_xor_sync(0xffffffffu, pl1, s);
            pr1 += __shfl_xor_sync(0xffffffffu, pr1, s);
        }
        if (lane == 0) {
            g_el[node0 * 2 + h] = pl0;
            g_er[node0 * 2 + h] = pr0;
            g_el[(node0 + 1) * 2 + h] = pl1;
            g_er[(node0 + 1) * 2 + h] = pr1;
        }
    }
}

// ---------------- edge pass 1: ee = exp(leaky(el[s]+er[d]+ew)), denom, deg ----------------
__global__ void k_edge1(const float* __restrict__ e_w,
                        const int* __restrict__ src,
                        const int* __restrict__ dst,
                        const float* __restrict__ attn_ew)
{
    int e = blockIdx.x * blockDim.x + threadIdx.x;
    if (e >= NE) return;
    int s = src[e], d = dst[e];
    float2 ew = ((const float2*)e_w)[e];
    float2 a = ((const float2*)g_el)[s];
    float2 b = ((const float2*)g_er)[d];
    float w00 = __ldg(&attn_ew[0]), w01 = __ldg(&attn_ew[1]);
    float w10 = __ldg(&attn_ew[2]), w11 = __ldg(&attn_ew[3]);

    float v0 = a.x + b.x + ew.x * w00 + ew.y * w01;
    float v1 = a.y + b.y + ew.x * w10 + ew.y * w11;
    v0 = v0 > 0.f ? v0 : 0.2f * v0;
    v1 = v1 > 0.f ? v1 : 0.2f * v1;
    float ee0 = __expf(v0);
    float ee1 = __expf(v1);
    ((float2*)g_ee)[e] = make_float2(ee0, ee1);
    atomicAdd(&g_denom[d * 2 + 0], ee0);
    atomicAdd(&g_denom[d * 2 + 1], ee1);
    atomicAdd(&g_deg[d], 1);
}

// ---------------- multi-block chained exclusive scan (13 blocks, 1 pass) ----------------
#define SCAN_NBLK 13
__global__ void __launch_bounds__(1024) k_scan() {
    __shared__ int wsum[32];
    __shared__ int s_tot, s_carry;
    const int n4 = NN / 4;   // 12500
    int b = blockIdx.x, t = threadIdx.x, lane = t & 31, w = t >> 5;
    int i = b * 1024 + t;

    int4 x = (i < n4) ? ((const int4*)g_deg)[i] : make_int4(0, 0, 0, 0);
    int s0 = x.x, s1 = s0 + x.y, s2 = s1 + x.z, s3 = s2 + x.w;
    int incl = s3;
#pragma unroll
    for (int s = 1; s < 32; s <<= 1) {
        int v = __shfl_up_sync(0xffffffffu, incl, s);
        if (lane >= s) incl += v;
    }
    if (lane == 31) wsum[w] = incl;
    __syncthreads();
    if (w == 0) {
        int ws = wsum[lane];
        int wi = ws;
#pragma unroll
        for (int s = 1; s < 32; s <<= 1) {
            int v = __shfl_up_sync(0xffffffffu, wi, s);
            if (lane >= s) wi += v;
        }
        wsum[lane] = wi - ws;          // exclusive warp offset
        if (lane == 31) s_tot = wi;    // block total
    }
    __syncthreads();

    if (t == 0) {
        int carry = 0;
        if (b > 0) {
            long long v;
            do { v = g_binc[b - 1]; } while (v < 0);
            carry = (int)v;
        }
        __threadfence();
        g_binc[b] = (long long)(carry + s_tot);
        s_carry = carry;
    }
    __syncthreads();

    if (i < n4) {
        int ex = s_carry + wsum[w] + incl - s3;
        ((int4*)g_off)[i] = make_int4(ex, ex + s0, ex + s1, ex + s2);
        if (i == n4 - 1) g_off[NN] = ex + s3;
    }
}

// ---------------- edge pass 2: counting-sort scatter ----------------
__global__ void k_edge2(const int* __restrict__ src,
                        const int* __restrict__ dst)
{
    int e = blockIdx.x * blockDim.x + threadIdx.x;
    if (e >= NE) return;
    int d = dst[e];
    int pos = atomicAdd(&g_cnt[d], 1);
    int idx = g_off[d] + pos;
    g_ssrc[idx] = src[e];
    ((float2*)g_see)[idx] = ((const float2*)g_ee)[e];
}

// ---------------- aggregation: one block per dst node, fp16 gather ----------------
__global__ void __launch_bounds__(128) k_agg(const float* __restrict__ feat,
                                             float* __restrict__ out)
{
    __shared__ int   ssrc[128];
    __shared__ float sa[256];
    int d = blockIdx.x;
    int t = threadIdx.x;
    int h = t >> 6;            // head
    int o2 = t & 63;           // half2 index within head (o = 2*o2, 2*o2+1)
    int beg = g_off[d], end = g_off[d + 1];
    float accx = 0.0f, accy = 0.0f;

    const __half2* fth2 = (const __half2*)g_fth;   // [n][128] half2 per node

    for (int base = beg; base < end; base += 128) {
        int n = min(128, end - base);
        if (t < n) ssrc[t] = g_ssrc[base + t];
        if (t < n) ((float2*)sa)[t] = ((const float2*)g_see)[base + t];
        __syncthreads();
        int j = 0;
        for (; j + 4 <= n; j += 4) {
            int s0 = ssrc[j], s1 = ssrc[j + 1], s2 = ssrc[j + 2], s3 = ssrc[j + 3];
            __half2 f0 = __ldg(&fth2[(size_t)s0 * 128 + t]);
            __half2 f1 = __ldg(&fth2[(size_t)s1 * 128 + t]);
            __half2 f2 = __ldg(&fth2[(size_t)s2 * 128 + t]);
            __half2 f3 = __ldg(&fth2[(size_t)s3 * 128 + t]);
            float2 v0 = __half22float2(f0);
            float2 v1 = __half22float2(f1);
            float2 v2 = __half22float2(f2);
            float2 v3 = __half22float2(f3);
            float a0 = sa[2 * j + h], a1 = sa[2 * j + 2 + h];
            float a2 = sa[2 * j + 4 + h], a3 = sa[2 * j + 6 + h];
            accx += v0.x * a0 + v1.x * a1 + v2.x * a2 + v3.x * a3;
            accy += v0.y * a0 + v1.y * a1 + v2.y * a2 + v3.y * a3;
        }
        for (; j < n; j++) {
            float2 v = __half22float2(__ldg(&fth2[(size_t)ssrc[j] * 128 + t]));
            float a = sa[2 * j + h];
            accx += v.x * a;
            accy += v.y * a;
        }
        __syncthreads();
    }

    float den = g_denom[d * 2 + h];
    float inv = den > 0.f ? 1.0f / den : 0.0f;
    float2 res = ((const float2*)feat)[(size_t)d * 64 + o2];
    float rx = accx * inv + res.x;
    float ry = accy * inv + res.y;
    rx = rx > 0.f ? rx : (__expf(rx) - 1.0f);
    ry = ry > 0.f ? ry : (__expf(ry) - 1.0f);
    ((float2*)out)[(size_t)d * 128 + h * 64 + o2] = make_float2(rx, ry);
}

// ---------------- launcher ----------------
extern "C" void kernel_launch(void* const* d_in, const int* in_sizes, int n_in,
                              void* d_out, int out_size)
{
    const float* feat    = (const float*)d_in[0];
    const float* e_w     = (const float*)d_in[1];
    const int*   src     = (const int*)  d_in[2];
    const int*   dst     = (const int*)  d_in[3];
    const float* W       = (const float*)d_in[4];
    const float* attn_l  = (const float*)d_in[5];
    const float* attn_r  = (const float*)d_in[6];
    const float* attn_ew = (const float*)d_in[7];
    float* out = (float*)d_out;

    k_setup<<<(NH + 255) / 256, 256>>>(W);
    k_gemm<<<NN / NT, 128>>>(feat, attn_l, attn_r);
    k_edge1<<<(NE + 255) / 256, 256>>>(e_w, src, dst, attn_ew);
    k_scan<<<SCAN_NBLK, 1024>>>();
    k_edge2<<<(NE + 255) / 256, 256>>>(src, dst);
    k_agg<<<NN, 128>>>(feat, out);
}

// round 5
// speedup vs baseline: 2.2235x; 1.4326x over previous
#include <cuda_runtime.h>
#include <cuda_fp16.h>

// Problem constants (fixed by the reference)
#define NN 50000
#define NE 800000
#define HEADS 2
#define OF 128
#define IF 128
#define NHO (NN*HEADS*OF)
#define NH  (NN*HEADS)

// ---------------- scratch (device globals; no runtime alloc) ----------------
__device__ __half   g_fth[NHO];         // [n][h][o] projected features, fp16
__device__ float    g_el[NH];
__device__ float    g_er[NH];
__device__ float    g_ee[NE*HEADS];     // per-edge exp values
__device__ float    g_denom[NH];
__device__ int      g_deg[NN];
__device__ int      g_off[NN+4];
__device__ int      g_pos[NE];          // within-dst rank of each edge
__device__ int      g_ssrc[NE];         // dst-sorted src ids
__device__ float    g_see[NE*HEADS];    // dst-sorted exp values
__device__ uint2    g_Wf[HEADS*16*8*32]; // W packed as mma B-fragments (64KB)
__device__ volatile unsigned long long g_binc[16]; // scan lookback states

// ---------------- setup: zero accumulators + pack W fragments ----------------
__global__ void k_setup(const float* __restrict__ W) {
    int i = blockIdx.x * blockDim.x + threadIdx.x;
    if (i < NH) g_denom[i] = 0.0f;
    if (i < NN) g_deg[i] = 0;
    if (i < 16) g_binc[i] = 0ull;
    // pack B fragments: index = ((h*16+nt)*8+ks)*32 + lane
    if (i < HEADS * 16 * 8 * 32) {
        int lane = i & 31;
        int ks = (i >> 5) & 7;
        int nt = (i >> 8) & 15;
        int h  = i >> 12;
        int tig = lane & 3, gid = lane >> 2;
        int n = nt * 8 + gid;          // output col within head
        int k0 = ks * 16 + 2 * tig;
        const float* Wh = W + h * 16384 + n * 128;  // W[h][o=n][i=k]
        __half2 b0 = __floats2half2_rn(Wh[k0],     Wh[k0 + 1]);
        __half2 b1 = __floats2half2_rn(Wh[k0 + 8], Wh[k0 + 9]);
        uint2 u;
        u.x = *(unsigned*)&b0;
        u.y = *(unsigned*)&b1;
        g_Wf[i] = u;
    }
}

// ---------------- projection GEMM: tensor cores (fp16 in, fp32 acc) ----------------
// Block: 128 threads = 4 warps, 16 nodes. Warp w: head h=w>>1, o-half=(w&1)*64.
#define SROW 136   // padded smem row (halves): conflict-free fragment loads
__global__ void __launch_bounds__(128) k_gemm(
    const float* __restrict__ feat,
    const float* __restrict__ attn_l,
    const float* __restrict__ attn_r)
{
    __shared__ __half sA[16 * SROW];
    __shared__ float s_el[16][2][2], s_er[16][2][2];

    int t = threadIdx.x;
    int n0 = blockIdx.x * 16;

    // load 16x128 fp32 feat tile, convert to fp16, store padded
    {
        const float4* fsrc = (const float4*)(feat + (size_t)n0 * IF);
#pragma unroll
        for (int k2 = 0; k2 < 4; k2++) {
            int g = t + k2 * 128;
            float4 v = fsrc[g];
            int node = g >> 5, c4 = g & 31;
            __half2 h0 = __floats2half2_rn(v.x, v.y);
            __half2 h1 = __floats2half2_rn(v.z, v.w);
            uint2 u;
            u.x = *(unsigned*)&h0;
            u.y = *(unsigned*)&h1;
            *(uint2*)&sA[node * SROW + c4 * 4] = u;
        }
    }
    __syncthreads();

    int w = t >> 5, lane = t & 31;
    int h = w >> 1, half64 = w & 1;
    int gid = lane >> 2, tig = lane & 3;
    int o_base = half64 * 64;

    float c[8][4];
#pragma unroll
    for (int nt = 0; nt < 8; nt++) { c[nt][0]=0.f; c[nt][1]=0.f; c[nt][2]=0.f; c[nt][3]=0.f; }

#pragma unroll
    for (int ks = 0; ks < 8; ks++) {
        const __half* ar = sA + gid * SROW + ks * 16 + 2 * tig;
        unsigned a0 = *(const unsigned*)(ar);
        unsigned a1 = *(const unsigned*)(ar + 8 * SROW);
        unsigned a2 = *(const unsigned*)(ar + 8);
        unsigned a3 = *(const unsigned*)(ar + 8 * SROW + 8);
#pragma unroll
        for (int nt = 0; nt < 8; nt++) {
            uint2 b = __ldg(&g_Wf[(((h * 16 + half64 * 8 + nt) * 8) + ks) * 32 + lane]);
            asm volatile(
                "mma.sync.aligned.m16n8k16.row.col.f32.f16.f16.f32 "
                "{%0,%1,%2,%3}, {%4,%5,%6,%7}, {%8,%9}, {%0,%1,%2,%3};"
                : "+f"(c[nt][0]), "+f"(c[nt][1]), "+f"(c[nt][2]), "+f"(c[nt][3])
                : "r"(a0), "r"(a1), "r"(a2), "r"(a3), "r"(b.x), "r"(b.y));
        }
    }

    // epilogue: store ft (fp16) + reduce el/er from fp32 accumulators
    float pl0 = 0.f, pl1 = 0.f, pr0 = 0.f, pr1 = 0.f;
#pragma unroll
    for (int nt = 0; nt < 8; nt++) {
        int o = o_base + nt * 8 + 2 * tig;
        float al0 = __ldg(&attn_l[h * 128 + o]), al1 = __ldg(&attn_l[h * 128 + o + 1]);
        float ar0 = __ldg(&attn_r[h * 128 + o]), ar1 = __ldg(&attn_r[h * 128 + o + 1]);
        pl0 += c[nt][0] * al0 + c[nt][1] * al1;
        pr0 += c[nt][0] * ar0 + c[nt][1] * ar1;
        pl1 += c[nt][2] * al0 + c[nt][3] * al1;
        pr1 += c[nt][2] * ar0 + c[nt][3] * ar1;
        __half2 lo = __floats2half2_rn(c[nt][0], c[nt][1]);
        __half2 hi = __floats2half2_rn(c[nt][2], c[nt][3]);
        ((unsigned*)g_fth)[(size_t)(n0 + gid) * 128 + h * 64 + (o >> 1)] = *(unsigned*)&lo;
        ((unsigned*)g_fth)[(size_t)(n0 + gid + 8) * 128 + h * 64 + (o >> 1)] = *(unsigned*)&hi;
    }
    // reduce over tig (quad)
    pl0 += __shfl_xor_sync(0xffffffffu, pl0, 1); pl0 += __shfl_xor_sync(0xffffffffu, pl0, 2);
    pr0 += __shfl_xor_sync(0xffffffffu, pr0, 1); pr0 += __shfl_xor_sync(0xffffffffu, pr0, 2);
    pl1 += __shfl_xor_sync(0xffffffffu, pl1, 1); pl1 += __shfl_xor_sync(0xffffffffu, pl1, 2);
    pr1 += __shfl_xor_sync(0xffffffffu, pr1, 1); pr1 += __shfl_xor_sync(0xffffffffu, pr1, 2);
    if (tig == 0) {
        s_el[gid][h][half64] = pl0;     s_er[gid][h][half64] = pr0;
        s_el[gid + 8][h][half64] = pl1; s_er[gid + 8][h][half64] = pr1;
    }
    __syncthreads();
    if (t < 32) {
        int node = t >> 1, hh = t & 1;
        g_el[(n0 + node) * 2 + hh] = s_el[node][hh][0] + s_el[node][hh][1];
        g_er[(n0 + node) * 2 + hh] = s_er[node][hh][0] + s_er[node][hh][1];
    }
}

// ---------------- edge pass 1: ee = exp(leaky(el[s]+er[d]+ew)), denom, deg+rank ----------------
__global__ void k_edge1(const float* __restrict__ e_w,
                        const int* __restrict__ src,
                        const int* __restrict__ dst,
                        const float* __restrict__ attn_ew)
{
    int e = blockIdx.x * blockDim.x + threadIdx.x;
    if (e >= NE) return;
    int s = src[e], d = dst[e];
    float2 ew = ((const float2*)e_w)[e];
    float2 a = ((const float2*)g_el)[s];
    float2 b = ((const float2*)g_er)[d];
    float w00 = __ldg(&attn_ew[0]), w01 = __ldg(&attn_ew[1]);
    float w10 = __ldg(&attn_ew[2]), w11 = __ldg(&attn_ew[3]);

    float v0 = a.x + b.x + ew.x * w00 + ew.y * w01;
    float v1 = a.y + b.y + ew.x * w10 + ew.y * w11;
    v0 = v0 > 0.f ? v0 : 0.2f * v0;
    v1 = v1 > 0.f ? v1 : 0.2f * v1;
    float ee0 = __expf(v0);
    float ee1 = __expf(v1);
    ((float2*)g_ee)[e] = make_float2(ee0, ee1);
    atomicAdd(&g_denom[d * 2 + 0], ee0);
    atomicAdd(&g_denom[d * 2 + 1], ee1);
    g_pos[e] = atomicAdd(&g_deg[d], 1);   // rank doubles as counting-sort slot
}

// ---------------- decoupled-lookback exclusive scan (13 blocks) ----------------
#define SCAN_NBLK 13
__global__ void __launch_bounds__(1024) k_scan() {
    __shared__ int wsum[32];
    __shared__ int s_tot, s_carry;
    const int n4 = NN / 4;   // 12500
    int b = blockIdx.x, t = threadIdx.x, lane = t & 31, w = t >> 5;
    int i = b * 1024 + t;

    int4 x = (i < n4) ? ((const int4*)g_deg)[i] : make_int4(0, 0, 0, 0);
    int s0 = x.x, s1 = s0 + x.y, s2 = s1 + x.z, s3 = s2 + x.w;
    int incl = s3;
#pragma unroll
    for (int s = 1; s < 32; s <<= 1) {
        int v = __shfl_up_sync(0xffffffffu, incl, s);
        if (lane >= s) incl += v;
    }
    if (lane == 31) wsum[w] = incl;
    __syncthreads();
    if (w == 0) {
        int ws = wsum[lane];
        int wi = ws;
#pragma unroll
        for (int s = 1; s < 32; s <<= 1) {
            int v = __shfl_up_sync(0xffffffffu, wi, s);
            if (lane >= s) wi += v;
        }
        wsum[lane] = wi - ws;
        if (lane == 31) s_tot = wi;
    }
    __syncthreads();

    if (t == 0) {
        if (b == 0) {
            g_binc[0] = (2ull << 32) | (unsigned)s_tot;   // prefix ready
            s_carry = 0;
        } else {
            g_binc[b] = (1ull << 32) | (unsigned)s_tot;   // aggregate ready
            long long carry = 0;
            int j = b - 1;
            while (j >= 0) {
                unsigned long long v;
                do { v = g_binc[j]; } while ((v >> 32) == 0ull);
                carry += (unsigned)v;
                if ((v >> 32) == 2ull) break;
                j--;
            }
            g_binc[b] = (2ull << 32) | (unsigned long long)(carry + s_tot);
            s_carry = (int)carry;
        }
    }
    __syncthreads();

    if (i < n4) {
        int ex = s_carry + wsum[w] + incl - s3;
        ((int4*)g_off)[i] = make_int4(ex, ex + s0, ex + s1, ex + s2);
        if (i == n4 - 1) g_off[NN] = ex + s3;
    }
}

// ---------------- edge pass 2: counting-sort scatter (atomic-free) ----------------
__global__ void k_edge2(const int* __restrict__ src,
                        const int* __restrict__ dst)
{
    int e = blockIdx.x * blockDim.x + threadIdx.x;
    if (e >= NE) return;
    int d = dst[e];
    int idx = g_off[d] + g_pos[e];
    g_ssrc[idx] = src[e];
    ((float2*)g_see)[idx] = ((const float2*)g_ee)[e];
}

// ---------------- aggregation: one block per dst node, fp16 gather ----------------
__global__ void __launch_bounds__(128) k_agg(const float* __restrict__ feat,
                                             float* __restrict__ out)
{
    __shared__ int   ssrc[128];
    __shared__ float sa[256];
    int d = blockIdx.x;
    int t = threadIdx.x;
    int h = t >> 6;
    int o2 = t & 63;
    int beg = g_off[d], end = g_off[d + 1];
    float accx = 0.0f, accy = 0.0f;

    const __half2* fth2 = (const __half2*)g_fth;

    for (int base = beg; base < end; base += 128) {
        int n = min(128, end - base);
        if (t < n) ssrc[t] = g_ssrc[base + t];
        if (t < n) ((float2*)sa)[t] = ((const float2*)g_see)[base + t];
        __syncthreads();
        int j = 0;
        for (; j + 4 <= n; j += 4) {
            int s0 = ssrc[j], s1 = ssrc[j + 1], s2 = ssrc[j + 2], s3 = ssrc[j + 3];
            float2 v0 = __half22float2(__ldg(&fth2[(size_t)s0 * 128 + t]));
            float2 v1 = __half22float2(__ldg(&fth2[(size_t)s1 * 128 + t]));
            float2 v2 = __half22float2(__ldg(&fth2[(size_t)s2 * 128 + t]));
            float2 v3 = __half22float2(__ldg(&fth2[(size_t)s3 * 128 + t]));
            float a0 = sa[2 * j + h], a1 = sa[2 * j + 2 + h];
            float a2 = sa[2 * j + 4 + h], a3 = sa[2 * j + 6 + h];
            accx += v0.x * a0 + v1.x * a1 + v2.x * a2 + v3.x * a3;
            accy += v0.y * a0 + v1.y * a1 + v2.y * a2 + v3.y * a3;
        }
        for (; j < n; j++) {
            float2 v = __half22float2(__ldg(&fth2[(size_t)ssrc[j] * 128 + t]));
            float a = sa[2 * j + h];
            accx += v.x * a;
            accy += v.y * a;
        }
        __syncthreads();
    }

    float den = g_denom[d * 2 + h];
    float inv = den > 0.f ? 1.0f / den : 0.0f;
    float2 res = ((const float2*)feat)[(size_t)d * 64 + o2];
    float rx = accx * inv + res.x;
    float ry = accy * inv + res.y;
    rx = rx > 0.f ? rx : (__expf(rx) - 1.0f);
    ry = ry > 0.f ? ry : (__expf(ry) - 1.0f);
    ((float2*)out)[(size_t)d * 128 + h * 64 + o2] = make_float2(rx, ry);
}

// ---------------- launcher ----------------
extern "C" void kernel_launch(void* const* d_in, const int* in_sizes, int n_in,
                              void* d_out, int out_size)
{
    const float* feat    = (const float*)d_in[0];
    const float* e_w     = (const float*)d_in[1];
    const int*   src     = (const int*)  d_in[2];
    const int*   dst     = (const int*)  d_in[3];
    const float* W       = (const float*)d_in[4];
    const float* attn_l  = (const float*)d_in[5];
    const float* attn_r  = (const float*)d_in[6];
    const float* attn_ew = (const float*)d_in[7];
    float* out = (float*)d_out;

    k_setup<<<(NH + 255) / 256, 256>>>(W);
    k_gemm<<<NN / 16, 128>>>(feat, attn_l, attn_r);
    k_edge1<<<(NE + 255) / 256, 256>>>(e_w, src, dst, attn_ew);
    k_scan<<<SCAN_NBLK, 1024>>>();
    k_edge2<<<(NE + 255) / 256, 256>>>(src, dst);
    k_agg<<<NN, 128>>>(feat, out);
}

// round 6
// speedup vs baseline: 2.3198x; 1.0433x over previous
#include <cuda_runtime.h>
#include <cuda_fp16.h>

// Problem constants (fixed by the reference)
#define NN 50000
#define NE 800000
#define HEADS 2
#define OF 128
#define IF 128
#define NHO (NN*HEADS*OF)
#define NH  (NN*HEADS)

// ---------------- scratch (device globals; no runtime alloc) ----------------
__device__ __half   g_fth[NHO];         // [n][h][o] projected features, fp16
__device__ float    g_el[NH];
__device__ float    g_er[NH];
__device__ float    g_denom[NH];
__device__ int      g_deg[NN];
__device__ int      g_off[NN+4];
__device__ int      g_pos[NE];          // within-dst rank of each edge
__device__ int4     g_edge[NE];         // dst-sorted (src, ee0, ee1, pad)
__device__ uint2    g_Wf[HEADS*16*8*32]; // W packed as mma B-fragments (64KB)
__device__ volatile unsigned long long g_binc[16]; // scan lookback states

// ---------------- setup: zero accumulators + pack W fragments ----------------
__global__ void k_setup(const float* __restrict__ W) {
    int i = blockIdx.x * blockDim.x + threadIdx.x;
    if (i < NH) g_denom[i] = 0.0f;
    if (i < NN) g_deg[i] = 0;
    if (i < 16) g_binc[i] = 0ull;
    // pack B fragments: index = ((h*16+nt)*8+ks)*32 + lane
    if (i < HEADS * 16 * 8 * 32) {
        int lane = i & 31;
        int ks = (i >> 5) & 7;
        int nt = (i >> 8) & 15;
        int h  = i >> 12;
        int tig = lane & 3, gid = lane >> 2;
        int n = nt * 8 + gid;          // output col within head
        int k0 = ks * 16 + 2 * tig;
        const float* Wh = W + h * 16384 + n * 128;  // W[h][o=n][i=k]
        __half2 b0 = __floats2half2_rn(Wh[k0],     Wh[k0 + 1]);
        __half2 b1 = __floats2half2_rn(Wh[k0 + 8], Wh[k0 + 9]);
        uint2 u;
        u.x = *(unsigned*)&b0;
        u.y = *(unsigned*)&b1;
        g_Wf[i] = u;
    }
}

// ---------------- histogram: degree + within-dst rank (dst only) ----------------
__global__ void k_hist(const int* __restrict__ dst) {
    int e4 = blockIdx.x * blockDim.x + threadIdx.x;
    if (e4 >= NE / 4) return;
    int4 d = ((const int4*)dst)[e4];
    g_pos[4 * e4 + 0] = atomicAdd(&g_deg[d.x], 1);
    g_pos[4 * e4 + 1] = atomicAdd(&g_deg[d.y], 1);
    g_pos[4 * e4 + 2] = atomicAdd(&g_deg[d.z], 1);
    g_pos[4 * e4 + 3] = atomicAdd(&g_deg[d.w], 1);
}

// ---------------- projection GEMM: tensor cores (fp16 in, fp32 acc) ----------------
// Block: 128 threads = 4 warps, 16 nodes. Warp w: head h=w>>1, o-half=(w&1)*64.
#define SROW 136   // padded smem row (halves): conflict-free fragment loads
__global__ void __launch_bounds__(128) k_gemm(
    const float* __restrict__ feat,
    const float* __restrict__ attn_l,
    const float* __restrict__ attn_r)
{
    __shared__ __half sA[16 * SROW];
    __shared__ float s_el[16][2][2], s_er[16][2][2];

    int t = threadIdx.x;
    int n0 = blockIdx.x * 16;

    // load 16x128 fp32 feat tile, convert to fp16, store padded
    {
        const float4* fsrc = (const float4*)(feat + (size_t)n0 * IF);
#pragma unroll
        for (int k2 = 0; k2 < 4; k2++) {
            int g = t + k2 * 128;
            float4 v = fsrc[g];
            int node = g >> 5, c4 = g & 31;
            __half2 h0 = __floats2half2_rn(v.x, v.y);
            __half2 h1 = __floats2half2_rn(v.z, v.w);
            uint2 u;
            u.x = *(unsigned*)&h0;
            u.y = *(unsigned*)&h1;
            *(uint2*)&sA[node * SROW + c4 * 4] = u;
        }
    }
    __syncthreads();

    int w = t >> 5, lane = t & 31;
    int h = w >> 1, half64 = w & 1;
    int gid = lane >> 2, tig = lane & 3;
    int o_base = half64 * 64;

    float c[8][4];
#pragma unroll
    for (int nt = 0; nt < 8; nt++) { c[nt][0]=0.f; c[nt][1]=0.f; c[nt][2]=0.f; c[nt][3]=0.f; }

#pragma unroll
    for (int ks = 0; ks < 8; ks++) {
        const __half* ar = sA + gid * SROW + ks * 16 + 2 * tig;
        unsigned a0 = *(const unsigned*)(ar);
        unsigned a1 = *(const unsigned*)(ar + 8 * SROW);
        unsigned a2 = *(const unsigned*)(ar + 8);
        unsigned a3 = *(const unsigned*)(ar + 8 * SROW + 8);
#pragma unroll
        for (int nt = 0; nt < 8; nt++) {
            uint2 b = __ldg(&g_Wf[(((h * 16 + half64 * 8 + nt) * 8) + ks) * 32 + lane]);
            asm volatile(
                "mma.sync.aligned.m16n8k16.row.col.f32.f16.f16.f32 "
                "{%0,%1,%2,%3}, {%4,%5,%6,%7}, {%8,%9}, {%0,%1,%2,%3};"
                : "+f"(c[nt][0]), "+f"(c[nt][1]), "+f"(c[nt][2]), "+f"(c[nt][3])
                : "r"(a0), "r"(a1), "r"(a2), "r"(a3), "r"(b.x), "r"(b.y));
        }
    }

    // epilogue: store ft (fp16) + reduce el/er from fp32 accumulators
    float pl0 = 0.f, pl1 = 0.f, pr0 = 0.f, pr1 = 0.f;
#pragma unroll
    for (int nt = 0; nt < 8; nt++) {
        int o = o_base + nt * 8 + 2 * tig;
        float al0 = __ldg(&attn_l[h * 128 + o]), al1 = __ldg(&attn_l[h * 128 + o + 1]);
        float ar0 = __ldg(&attn_r[h * 128 + o]), ar1 = __ldg(&attn_r[h * 128 + o + 1]);
        pl0 += c[nt][0] * al0 + c[nt][1] * al1;
        pr0 += c[nt][0] * ar0 + c[nt][1] * ar1;
        pl1 += c[nt][2] * al0 + c[nt][3] * al1;
        pr1 += c[nt][2] * ar0 + c[nt][3] * ar1;
        __half2 lo = __floats2half2_rn(c[nt][0], c[nt][1]);
        __half2 hi = __floats2half2_rn(c[nt][2], c[nt][3]);
        ((unsigned*)g_fth)[(size_t)(n0 + gid) * 128 + h * 64 + (o >> 1)] = *(unsigned*)&lo;
        ((unsigned*)g_fth)[(size_t)(n0 + gid + 8) * 128 + h * 64 + (o >> 1)] = *(unsigned*)&hi;
    }
    // reduce over tig (quad)
    pl0 += __shfl_xor_sync(0xffffffffu, pl0, 1); pl0 += __shfl_xor_sync(0xffffffffu, pl0, 2);
    pr0 += __shfl_xor_sync(0xffffffffu, pr0, 1); pr0 += __shfl_xor_sync(0xffffffffu, pr0, 2);
    pl1 += __shfl_xor_sync(0xffffffffu, pl1, 1); pl1 += __shfl_xor_sync(0xffffffffu, pl1, 2);
    pr1 += __shfl_xor_sync(0xffffffffu, pr1, 1); pr1 += __shfl_xor_sync(0xffffffffu, pr1, 2);
    if (tig == 0) {
        s_el[gid][h][half64] = pl0;     s_er[gid][h][half64] = pr0;
        s_el[gid + 8][h][half64] = pl1; s_er[gid + 8][h][half64] = pr1;
    }
    __syncthreads();
    if (t < 32) {
        int node = t >> 1, hh = t & 1;
        g_el[(n0 + node) * 2 + hh] = s_el[node][hh][0] + s_el[node][hh][1];
        g_er[(n0 + node) * 2 + hh] = s_er[node][hh][0] + s_er[node][hh][1];
    }
}

// ---------------- decoupled-lookback exclusive scan (13 blocks) ----------------
#define SCAN_NBLK 13
__global__ void __launch_bounds__(1024) k_scan() {
    __shared__ int wsum[32];
    __shared__ int s_tot, s_carry;
    const int n4 = NN / 4;   // 12500
    int b = blockIdx.x, t = threadIdx.x, lane = t & 31, w = t >> 5;
    int i = b * 1024 + t;

    int4 x = (i < n4) ? ((const int4*)g_deg)[i] : make_int4(0, 0, 0, 0);
    int s0 = x.x, s1 = s0 + x.y, s2 = s1 + x.z, s3 = s2 + x.w;
    int incl = s3;
#pragma unroll
    for (int s = 1; s < 32; s <<= 1) {
        int v = __shfl_up_sync(0xffffffffu, incl, s);
        if (lane >= s) incl += v;
    }
    if (lane == 31) wsum[w] = incl;
    __syncthreads();
    if (w == 0) {
        int ws = wsum[lane];
        int wi = ws;
#pragma unroll
        for (int s = 1; s < 32; s <<= 1) {
            int v = __shfl_up_sync(0xffffffffu, wi, s);
            if (lane >= s) wi += v;
        }
        wsum[lane] = wi - ws;
        if (lane == 31) s_tot = wi;
    }
    __syncthreads();

    if (t == 0) {
        if (b == 0) {
            g_binc[0] = (2ull << 32) | (unsigned)s_tot;   // prefix ready
            s_carry = 0;
        } else {
            g_binc[b] = (1ull << 32) | (unsigned)s_tot;   // aggregate ready
            long long carry = 0;
            int j = b - 1;
            while (j >= 0) {
                unsigned long long v;
                do { v = g_binc[j]; } while ((v >> 32) == 0ull);
                carry += (unsigned)v;
                if ((v >> 32) == 2ull) break;
                j--;
            }
            g_binc[b] = (2ull << 32) | (unsigned long long)(carry + s_tot);
            s_carry = (int)carry;
        }
    }
    __syncthreads();

    if (i < n4) {
        int ex = s_carry + wsum[w] + incl - s3;
        ((int4*)g_off)[i] = make_int4(ex, ex + s0, ex + s1, ex + s2);
        if (i == n4 - 1) g_off[NN] = ex + s3;
    }
}

// ---------------- fused edge pass: ee + denom + direct sorted scatter ----------------
__global__ void k_edge(const float* __restrict__ e_w,
                       const int* __restrict__ src,
                       const int* __restrict__ dst,
                       const float* __restrict__ attn_ew)
{
    int e = blockIdx.x * blockDim.x + threadIdx.x;
    if (e >= NE) return;
    int s = src[e], d = dst[e];
    float2 ew = ((const float2*)e_w)[e];
    float2 a = ((const float2*)g_el)[s];
    float2 b = ((const float2*)g_er)[d];
    float w00 = __ldg(&attn_ew[0]), w01 = __ldg(&attn_ew[1]);
    float w10 = __ldg(&attn_ew[2]), w11 = __ldg(&attn_ew[3]);

    float v0 = a.x + b.x + ew.x * w00 + ew.y * w01;
    float v1 = a.y + b.y + ew.x * w10 + ew.y * w11;
    v0 = v0 > 0.f ? v0 : 0.2f * v0;
    v1 = v1 > 0.f ? v1 : 0.2f * v1;
    float ee0 = __expf(v0);
    float ee1 = __expf(v1);
    atomicAdd(&g_denom[d * 2 + 0], ee0);
    atomicAdd(&g_denom[d * 2 + 1], ee1);
    int idx = g_off[d] + g_pos[e];
    g_edge[idx] = make_int4(s, __float_as_int(ee0), __float_as_int(ee1), 0);
}

// ---------------- aggregation: one block per dst node, fp16 gather ----------------
__global__ void __launch_bounds__(128) k_agg(const float* __restrict__ feat,
                                             float* __restrict__ out)
{
    __shared__ int   ssrc[128];
    __shared__ float sa[256];
    int d = blockIdx.x;
    int t = threadIdx.x;
    int h = t >> 6;
    int o2 = t & 63;
    int beg = g_off[d], end = g_off[d + 1];
    float accx = 0.0f, accy = 0.0f;

    const __half2* fth2 = (const __half2*)g_fth;

    for (int base = beg; base < end; base += 128) {
        int n = min(128, end - base);
        if (t < n) {
            int4 v = g_edge[base + t];
            ssrc[t] = v.x;
            sa[2 * t + 0] = __int_as_float(v.y);
            sa[2 * t + 1] = __int_as_float(v.z);
        }
        __syncthreads();
        int j = 0;
        for (; j + 4 <= n; j += 4) {
            int s0 = ssrc[j], s1 = ssrc[j + 1], s2 = ssrc[j + 2], s3 = ssrc[j + 3];
            float2 v0 = __half22float2(__ldg(&fth2[(size_t)s0 * 128 + t]));
            float2 v1 = __half22float2(__ldg(&fth2[(size_t)s1 * 128 + t]));
            float2 v2 = __half22float2(__ldg(&fth2[(size_t)s2 * 128 + t]));
            float2 v3 = __half22float2(__ldg(&fth2[(size_t)s3 * 128 + t]));
            float a0 = sa[2 * j + h], a1 = sa[2 * j + 2 + h];
            float a2 = sa[2 * j + 4 + h], a3 = sa[2 * j + 6 + h];
            accx += v0.x * a0 + v1.x * a1 + v2.x * a2 + v3.x * a3;
            accy += v0.y * a0 + v1.y * a1 + v2.y * a2 + v3.y * a3;
        }
        for (; j < n; j++) {
            float2 v = __half22float2(__ldg(&fth2[(size_t)ssrc[j] * 128 + t]));
            float a = sa[2 * j + h];
            accx += v.x * a;
            accy += v.y * a;
        }
        __syncthreads();
    }

    float den = g_denom[d * 2 + h];
    float inv = den > 0.f ? 1.0f / den : 0.0f;
    float2 res = ((const float2*)feat)[(size_t)d * 64 + o2];
    float rx = accx * inv + res.x;
    float ry = accy * inv + res.y;
    rx = rx > 0.f ? rx : (__expf(rx) - 1.0f);
    ry = ry > 0.f ? ry : (__expf(ry) - 1.0f);
    ((float2*)out)[(size_t)d * 128 + h * 64 + o2] = make_float2(rx, ry);
}

// ---------------- launcher: fork-join so hist+scan overlap setup+gemm ----------------
extern "C" void kernel_launch(void* const* d_in, const int* in_sizes, int n_in,
                              void* d_out, int out_size)
{
    const float* feat    = (const float*)d_in[0];
    const float* e_w     = (const float*)d_in[1];
    const int*   src     = (const int*)  d_in[2];
    const int*   dst     = (const int*)  d_in[3];
    const float* W       = (const float*)d_in[4];
    const float* attn_l  = (const float*)d_in[5];
    const float* attn_r  = (const float*)d_in[6];
    const float* attn_ew = (const float*)d_in[7];
    float* out = (float*)d_out;

    cudaStream_t s2;
    cudaStreamCreate(&s2);
    cudaEvent_t evFork, evJoin;
    cudaEventCreateWithFlags(&evFork, cudaEventDisableTiming);
    cudaEventCreateWithFlags(&evJoin, cudaEventDisableTiming);

    k_setup<<<(NH + 255) / 256, 256>>>(W);
    cudaEventRecord(evFork, 0);

    // side stream: CSR build (depends only on dst + zeroed deg)
    cudaStreamWaitEvent(s2, evFork, 0);
    k_hist<<<(NE / 4 + 255) / 256, 256, 0, s2>>>(dst);
    k_scan<<<SCAN_NBLK, 1024, 0, s2>>>();
    cudaEventRecord(evJoin, s2);

    // main stream: projection GEMM
    k_gemm<<<NN / 16, 128>>>(feat, attn_l, attn_r);

    // join, then fused edge pass + aggregation
    cudaStreamWaitEvent(0, evJoin, 0);
    k_edge<<<(NE + 255) / 256, 256>>>(e_w, src, dst, attn_ew);
    k_agg<<<NN, 128>>>(feat, out);
}

// round 7
// speedup vs baseline: 2.4700x; 1.0647x over previous
#include <cuda_runtime.h>
#include <cuda_fp16.h>

// Problem constants (fixed by the reference)
#define NN 50000
#define NE 800000
#define HEADS 2
#define OF 128
#define IF 128
#define NHO (NN*HEADS*OF)
#define NH  (NN*HEADS)

// ---------------- scratch (device globals; no runtime alloc) ----------------
__device__ __half   g_fth[NHO];         // [n][h][o] projected features, fp16
__device__ float    g_el[NH];
__device__ float    g_er[NH];
__device__ int      g_deg[NN];
__device__ int      g_off[NN+4];
__device__ int      g_pos[NE];          // within-dst rank of each edge
__device__ int2     g_eidx[NE];         // dst-sorted (src, edge_id)
__device__ uint2    g_Wf[HEADS*16*8*32]; // W packed as mma B-fragments (64KB)
__device__ volatile unsigned long long g_binc[16]; // scan lookback states

// ---------------- setup: zero counters + pack W fragments ----------------
__global__ void k_setup(const float* __restrict__ W) {
    int i = blockIdx.x * blockDim.x + threadIdx.x;
    if (i < NN) g_deg[i] = 0;
    if (i < 16) g_binc[i] = 0ull;
    // pack B fragments: index = ((h*16+nt)*8+ks)*32 + lane
    if (i < HEADS * 16 * 8 * 32) {
        int lane = i & 31;
        int ks = (i >> 5) & 7;
        int nt = (i >> 8) & 15;
        int h  = i >> 12;
        int tig = lane & 3, gid = lane >> 2;
        int n = nt * 8 + gid;          // output col within head
        int k0 = ks * 16 + 2 * tig;
        const float* Wh = W + h * 16384 + n * 128;  // W[h][o=n][i=k]
        __half2 b0 = __floats2half2_rn(Wh[k0],     Wh[k0 + 1]);
        __half2 b1 = __floats2half2_rn(Wh[k0 + 8], Wh[k0 + 9]);
        uint2 u;
        u.x = *(unsigned*)&b0;
        u.y = *(unsigned*)&b1;
        g_Wf[i] = u;
    }
}

// ---------------- histogram: degree + within-dst rank (dst only) ----------------
__global__ void k_hist(const int* __restrict__ dst) {
    int e4 = blockIdx.x * blockDim.x + threadIdx.x;
    if (e4 >= NE / 4) return;
    int4 d = ((const int4*)dst)[e4];
    g_pos[4 * e4 + 0] = atomicAdd(&g_deg[d.x], 1);
    g_pos[4 * e4 + 1] = atomicAdd(&g_deg[d.y], 1);
    g_pos[4 * e4 + 2] = atomicAdd(&g_deg[d.z], 1);
    g_pos[4 * e4 + 3] = atomicAdd(&g_deg[d.w], 1);
}

// ---------------- decoupled-lookback exclusive scan (13 blocks) ----------------
#define SCAN_NBLK 13
__global__ void __launch_bounds__(1024) k_scan() {
    __shared__ int wsum[32];
    __shared__ int s_tot, s_carry;
    const int n4 = NN / 4;   // 12500
    int b = blockIdx.x, t = threadIdx.x, lane = t & 31, w = t >> 5;
    int i = b * 1024 + t;

    int4 x = (i < n4) ? ((const int4*)g_deg)[i] : make_int4(0, 0, 0, 0);
    int s0 = x.x, s1 = s0 + x.y, s2 = s1 + x.z, s3 = s2 + x.w;
    int incl = s3;
#pragma unroll
    for (int s = 1; s < 32; s <<= 1) {
        int v = __shfl_up_sync(0xffffffffu, incl, s);
        if (lane >= s) incl += v;
    }
    if (lane == 31) wsum[w] = incl;
    __syncthreads();
    if (w == 0) {
        int ws = wsum[lane];
        int wi = ws;
#pragma unroll
        for (int s = 1; s < 32; s <<= 1) {
            int v = __shfl_up_sync(0xffffffffu, wi, s);
            if (lane >= s) wi += v;
        }
        wsum[lane] = wi - ws;
        if (lane == 31) s_tot = wi;
    }
    __syncthreads();

    if (t == 0) {
        if (b == 0) {
            g_binc[0] = (2ull << 32) | (unsigned)s_tot;
            s_carry = 0;
        } else {
            g_binc[b] = (1ull << 32) | (unsigned)s_tot;
            long long carry = 0;
            int j = b - 1;
            while (j >= 0) {
                unsigned long long v;
                do { v = g_binc[j]; } while ((v >> 32) == 0ull);
                carry += (unsigned)v;
                if ((v >> 32) == 2ull) break;
                j--;
            }
            g_binc[b] = (2ull << 32) | (unsigned long long)(carry + s_tot);
            s_carry = (int)carry;
        }
    }
    __syncthreads();

    if (i < n4) {
        int ex = s_carry + wsum[w] + incl - s3;
        ((int4*)g_off)[i] = make_int4(ex, ex + s0, ex + s1, ex + s2);
        if (i == n4 - 1) g_off[NN] = ex + s3;
    }
}

// ---------------- scatter: (src, edge_id) into dst-sorted order ----------------
__global__ void k_scatter(const int* __restrict__ src,
                          const int* __restrict__ dst)
{
    int e = blockIdx.x * blockDim.x + threadIdx.x;
    if (e >= NE) return;
    int d = dst[e];
    int idx = g_off[d] + g_pos[e];
    g_eidx[idx] = make_int2(src[e], e);
}

// ---------------- projection GEMM: tensor cores, 32 nodes/block ----------------
#define SROW 136   // padded smem row (halves): conflict-free fragment loads
__global__ void __launch_bounds__(128) k_gemm(
    const float* __restrict__ feat,
    const float* __restrict__ attn_l,
    const float* __restrict__ attn_r)
{
    __shared__ __half sA[32 * SROW];
    __shared__ float s_el[32][2][2], s_er[32][2][2];

    int t = threadIdx.x;
    int n0 = blockIdx.x * 32;
    int nrem = NN - n0;                  // 32 normally, 16 for last block

    // load up to 32x128 fp32 feat tile, convert to fp16, store padded
    {
        const float4* fsrc = (const float4*)(feat + (size_t)n0 * IF);
#pragma unroll
        for (int k2 = 0; k2 < 8; k2++) {
            int g = t + k2 * 128;
            int node = g >> 5, c4 = g & 31;
            float4 v = (node < nrem) ? fsrc[g] : make_float4(0.f, 0.f, 0.f, 0.f);
            __half2 h0 = __floats2half2_rn(v.x, v.y);
            __half2 h1 = __floats2half2_rn(v.z, v.w);
            uint2 u;
            u.x = *(unsigned*)&h0;
            u.y = *(unsigned*)&h1;
            *(uint2*)&sA[node * SROW + c4 * 4] = u;
        }
    }
    __syncthreads();

    int w = t >> 5, lane = t & 31;
    int h = w >> 1, half64 = w & 1;
    int gid = lane >> 2, tig = lane & 3;
    int o_base = half64 * 64;

    float c[2][8][4];
#pragma unroll
    for (int tl = 0; tl < 2; tl++)
#pragma unroll
        for (int nt = 0; nt < 8; nt++) { c[tl][nt][0]=0.f; c[tl][nt][1]=0.f; c[tl][nt][2]=0.f; c[tl][nt][3]=0.f; }

#pragma unroll
    for (int ks = 0; ks < 8; ks++) {
        unsigned a[2][4];
#pragma unroll
        for (int tl = 0; tl < 2; tl++) {
            const __half* ar = sA + (tl * 16 + gid) * SROW + ks * 16 + 2 * tig;
            a[tl][0] = *(const unsigned*)(ar);
            a[tl][1] = *(const unsigned*)(ar + 8 * SROW);
            a[tl][2] = *(const unsigned*)(ar + 8);
            a[tl][3] = *(const unsigned*)(ar + 8 * SROW + 8);
        }
#pragma unroll
        for (int nt = 0; nt < 8; nt++) {
            uint2 b = __ldg(&g_Wf[(((h * 16 + half64 * 8 + nt) * 8) + ks) * 32 + lane]);
#pragma unroll
            for (int tl = 0; tl < 2; tl++) {
                asm volatile(
                    "mma.sync.aligned.m16n8k16.row.col.f32.f16.f16.f32 "
                    "{%0,%1,%2,%3}, {%4,%5,%6,%7}, {%8,%9}, {%0,%1,%2,%3};"
                    : "+f"(c[tl][nt][0]), "+f"(c[tl][nt][1]), "+f"(c[tl][nt][2]), "+f"(c[tl][nt][3])
                    : "r"(a[tl][0]), "r"(a[tl][1]), "r"(a[tl][2]), "r"(a[tl][3]),
                      "r"(b.x), "r"(b.y));
            }
        }
    }

    // epilogue per tile: store ft (fp16) + reduce el/er from fp32 accumulators
#pragma unroll
    for (int tl = 0; tl < 2; tl++) {
        if (n0 + tl * 16 >= NN) break;
        float pl0 = 0.f, pl1 = 0.f, pr0 = 0.f, pr1 = 0.f;
#pragma unroll
        for (int nt = 0; nt < 8; nt++) {
            int o = o_base + nt * 8 + 2 * tig;
            float al0 = __ldg(&attn_l[h * 128 + o]), al1 = __ldg(&attn_l[h * 128 + o + 1]);
            float ar0 = __ldg(&attn_r[h * 128 + o]), ar1 = __ldg(&attn_r[h * 128 + o + 1]);
            pl0 += c[tl][nt][0] * al0 + c[tl][nt][1] * al1;
            pr0 += c[tl][nt][0] * ar0 + c[tl][nt][1] * ar1;
            pl1 += c[tl][nt][2] * al0 + c[tl][nt][3] * al1;
            pr1 += c[tl][nt][2] * ar0 + c[tl][nt][3] * ar1;
            __half2 lo = __floats2half2_rn(c[tl][nt][0], c[tl][nt][1]);
            __half2 hi = __floats2half2_rn(c[tl][nt][2], c[tl][nt][3]);
            int nb = n0 + tl * 16 + gid;
            ((unsigned*)g_fth)[(size_t)nb * 128 + h * 64 + (o >> 1)] = *(unsigned*)&lo;
            ((unsigned*)g_fth)[(size_t)(nb + 8) * 128 + h * 64 + (o >> 1)] = *(unsigned*)&hi;
        }
        pl0 += __shfl_xor_sync(0xffffffffu, pl0, 1); pl0 += __shfl_xor_sync(0xffffffffu, pl0, 2);
        pr0 += __shfl_xor_sync(0xffffffffu, pr0, 1); pr0 += __shfl_xor_sync(0xffffffffu, pr0, 2);
        pl1 += __shfl_xor_sync(0xffffffffu, pl1, 1); pl1 += __shfl_xor_sync(0xffffffffu, pl1, 2);
        pr1 += __shfl_xor_sync(0xffffffffu, pr1, 1); pr1 += __shfl_xor_sync(0xffffffffu, pr1, 2);
        if (tig == 0) {
            s_el[tl * 16 + gid][h][half64] = pl0;     s_er[tl * 16 + gid][h][half64] = pr0;
            s_el[tl * 16 + gid + 8][h][half64] = pl1; s_er[tl * 16 + gid + 8][h][half64] = pr1;
        }
    }
    __syncthreads();
    if (t < 64) {
        int node = t >> 1, hh = t & 1;
        if (n0 + node < NN) {
            g_el[(n0 + node) * 2 + hh] = s_el[node][hh][0] + s_el[node][hh][1];
            g_er[(n0 + node) * 2 + hh] = s_er[node][hh][0] + s_er[node][hh][1];
        }
    }
}

// ---------------- aggregation: fused edge-softmax + gather, one block per dst ----------------
__global__ void __launch_bounds__(128) k_agg(const float* __restrict__ feat,
                                             const float* __restrict__ e_w,
                                             const float* __restrict__ attn_ew,
                                             float* __restrict__ out)
{
    __shared__ int   ssrc[128];
    __shared__ float sa[256];
    int d = blockIdx.x;
    int t = threadIdx.x;
    int h = t >> 6;
    int o2 = t & 63;
    int beg = g_off[d], end = g_off[d + 1];
    float accx = 0.0f, accy = 0.0f, dacc = 0.0f;

    float2 erd = ((const float2*)g_er)[d];
    float w00 = __ldg(&attn_ew[0]), w01 = __ldg(&attn_ew[1]);
    float w10 = __ldg(&attn_ew[2]), w11 = __ldg(&attn_ew[3]);

    const __half2* fth2 = (const __half2*)g_fth;

    for (int base = beg; base < end; base += 128) {
        int n = min(128, end - base);
        if (t < n) {
            int2 se = g_eidx[base + t];
            int s = se.x, e = se.y;
            float2 ew = __ldg(&((const float2*)e_w)[e]);
            float2 a = __ldg(&((const float2*)g_el)[s]);
            float v0 = a.x + erd.x + ew.x * w00 + ew.y * w01;
            float v1 = a.y + erd.y + ew.x * w10 + ew.y * w11;
            v0 = v0 > 0.f ? v0 : 0.2f * v0;
            v1 = v1 > 0.f ? v1 : 0.2f * v1;
            ssrc[t] = s;
            sa[2 * t + 0] = __expf(v0);
            sa[2 * t + 1] = __expf(v1);
        }
        __syncthreads();
        int j = 0;
        for (; j + 4 <= n; j += 4) {
            int s0 = ssrc[j], s1 = ssrc[j + 1], s2 = ssrc[j + 2], s3 = ssrc[j + 3];
            float2 v0 = __half22float2(__ldg(&fth2[(size_t)s0 * 128 + t]));
            float2 v1 = __half22float2(__ldg(&fth2[(size_t)s1 * 128 + t]));
            float2 v2 = __half22float2(__ldg(&fth2[(size_t)s2 * 128 + t]));
            float2 v3 = __half22float2(__ldg(&fth2[(size_t)s3 * 128 + t]));
            float a0 = sa[2 * j + h], a1 = sa[2 * j + 2 + h];
            float a2 = sa[2 * j + 4 + h], a3 = sa[2 * j + 6 + h];
            accx += v0.x * a0 + v1.x * a1 + v2.x * a2 + v3.x * a3;
            accy += v0.y * a0 + v1.y * a1 + v2.y * a2 + v3.y * a3;
            dacc += (a0 + a1) + (a2 + a3);
        }
        for (; j < n; j++) {
            float2 v = __half22float2(__ldg(&fth2[(size_t)ssrc[j] * 128 + t]));
            float a = sa[2 * j + h];
            accx += v.x * a;
            accy += v.y * a;
            dacc += a;
        }
        __syncthreads();
    }

    float inv = dacc > 0.f ? 1.0f / dacc : 0.0f;
    float2 res = ((const float2*)feat)[(size_t)d * 64 + o2];
    float rx = accx * inv + res.x;
    float ry = accy * inv + res.y;
    rx = rx > 0.f ? rx : (__expf(rx) - 1.0f);
    ry = ry > 0.f ? ry : (__expf(ry) - 1.0f);
    ((float2*)out)[(size_t)d * 128 + h * 64 + o2] = make_float2(rx, ry);
}

// ---------------- launcher: CSR build fully overlapped with GEMM ----------------
extern "C" void kernel_launch(void* const* d_in, const int* in_sizes, int n_in,
                              void* d_out, int out_size)
{
    const float* feat    = (const float*)d_in[0];
    const float* e_w     = (const float*)d_in[1];
    const int*   src     = (const int*)  d_in[2];
    const int*   dst     = (const int*)  d_in[3];
    const float* W       = (const float*)d_in[4];
    const float* attn_l  = (const float*)d_in[5];
    const float* attn_r  = (const float*)d_in[6];
    const float* attn_ew = (const float*)d_in[7];
    float* out = (float*)d_out;

    cudaStream_t s2;
    cudaStreamCreate(&s2);
    cudaEvent_t evFork, evJoin;
    cudaEventCreateWithFlags(&evFork, cudaEventDisableTiming);
    cudaEventCreateWithFlags(&evJoin, cudaEventDisableTiming);

    k_setup<<<(NN + 255) / 256, 256>>>(W);
    cudaEventRecord(evFork, 0);

    // side stream: full CSR build (depends only on dst/src + zeroed deg)
    cudaStreamWaitEvent(s2, evFork, 0);
    k_hist<<<(NE / 4 + 255) / 256, 256, 0, s2>>>(dst);
    k_scan<<<SCAN_NBLK, 1024, 0, s2>>>();
    k_scatter<<<(NE + 255) / 256, 256, 0, s2>>>(src, dst);
    cudaEventRecord(evJoin, s2);

    // main stream: projection GEMM
    k_gemm<<<(NN + 31) / 32, 128>>>(feat, attn_l, attn_r);

    // join, then fused softmax+aggregation
    cudaStreamWaitEvent(0, evJoin, 0);
    k_agg<<<NN, 128>>>(feat, e_w, attn_ew, out);
}

// round 9
// speedup vs baseline: 3.1347x; 1.2691x over previous
#include <cuda_runtime.h>
#include <cuda_fp16.h>

// Problem constants (fixed by the reference)
#define NN 50000
#define NE 800000
#define HEADS 2
#define OF 128
#define IF 128
#define NHO (NN*HEADS*OF)
#define NH  (NN*HEADS)

// ---------------- scratch (device globals; no runtime alloc) ----------------
__device__ __half   g_fth[NHO];         // [n][h][o] projected features, fp16
__device__ float    g_el[NH];
__device__ float    g_er[NH];
__device__ int      g_deg[NN];
__device__ int      g_off[NN+4];
__device__ int      g_pos[NE];          // within-dst rank of each edge
__device__ int2     g_eidx[NE];         // dst-sorted (src, edge_id)
__device__ uint2    g_Wf[HEADS*16*8*32]; // W packed as mma B-fragments (64KB)
__device__ volatile unsigned long long g_binc[16]; // scan lookback states

// ---------------- zero pass (side stream, no input deps) ----------------
__global__ void k_zero() {
    int i = blockIdx.x * blockDim.x + threadIdx.x;
    if (i < NN) g_deg[i] = 0;
    if (i < 16) g_binc[i] = 0ull;
}

// ---------------- setup: pack W fragments (main stream) ----------------
__global__ void k_setup(const float* __restrict__ W) {
    int i = blockIdx.x * blockDim.x + threadIdx.x;
    // pack B fragments: index = ((h*16+nt)*8+ks)*32 + lane
    if (i < HEADS * 16 * 8 * 32) {
        int lane = i & 31;
        int ks = (i >> 5) & 7;
        int nt = (i >> 8) & 15;
        int h  = i >> 12;
        int tig = lane & 3, gid = lane >> 2;
        int n = nt * 8 + gid;          // output col within head
        int k0 = ks * 16 + 2 * tig;
        const float* Wh = W + h * 16384 + n * 128;  // W[h][o=n][i=k]
        __half2 b0 = __floats2half2_rn(Wh[k0],     Wh[k0 + 1]);
        __half2 b1 = __floats2half2_rn(Wh[k0 + 8], Wh[k0 + 9]);
        uint2 u;
        u.x = *(unsigned*)&b0;
        u.y = *(unsigned*)&b1;
        g_Wf[i] = u;
    }
}

// ---------------- histogram: degree + within-dst rank (dst only) ----------------
__global__ void k_hist(const int* __restrict__ dst) {
    int e4 = blockIdx.x * blockDim.x + threadIdx.x;
    if (e4 >= NE / 4) return;
    int4 d = ((const int4*)dst)[e4];
    g_pos[4 * e4 + 0] = atomicAdd(&g_deg[d.x], 1);
    g_pos[4 * e4 + 1] = atomicAdd(&g_deg[d.y], 1);
    g_pos[4 * e4 + 2] = atomicAdd(&g_deg[d.z], 1);
    g_pos[4 * e4 + 3] = atomicAdd(&g_deg[d.w], 1);
}

// ---------------- decoupled-lookback exclusive scan (13 blocks) ----------------
#define SCAN_NBLK 13
__global__ void __launch_bounds__(1024) k_scan() {
    __shared__ int wsum[32];
    __shared__ int s_tot, s_carry;
    const int n4 = NN / 4;   // 12500
    int b = blockIdx.x, t = threadIdx.x, lane = t & 31, w = t >> 5;
    int i = b * 1024 + t;

    int4 x = (i < n4) ? ((const int4*)g_deg)[i] : make_int4(0, 0, 0, 0);
    int s0 = x.x, s1 = s0 + x.y, s2 = s1 + x.z, s3 = s2 + x.w;
    int incl = s3;
#pragma unroll
    for (int s = 1; s < 32; s <<= 1) {
        int v = __shfl_up_sync(0xffffffffu, incl, s);
        if (lane >= s) incl += v;
    }
    if (lane == 31) wsum[w] = incl;
    __syncthreads();
    if (w == 0) {
        int ws = wsum[lane];
        int wi = ws;
#pragma unroll
        for (int s = 1; s < 32; s <<= 1) {
            int v = __shfl_up_sync(0xffffffffu, wi, s);
            if (lane >= s) wi += v;
        }
        wsum[lane] = wi - ws;
        if (lane == 31) s_tot = wi;
    }
    __syncthreads();

    if (t == 0) {
        if (b == 0) {
            g_binc[0] = (2ull << 32) | (unsigned)s_tot;
            s_carry = 0;
        } else {
            g_binc[b] = (1ull << 32) | (unsigned)s_tot;
            long long carry = 0;
            int j = b - 1;
            while (j >= 0) {
                unsigned long long v;
                do { v = g_binc[j]; } while ((v >> 32) == 0ull);
                carry += (unsigned)v;
                if ((v >> 32) == 2ull) break;
                j--;
            }
            g_binc[b] = (2ull << 32) | (unsigned long long)(carry + s_tot);
            s_carry = (int)carry;
        }
    }
    __syncthreads();

    if (i < n4) {
        int ex = s_carry + wsum[w] + incl - s3;
        ((int4*)g_off)[i] = make_int4(ex, ex + s0, ex + s1, ex + s2);
        if (i == n4 - 1) g_off[NN] = ex + s3;
    }
}

// ---------------- scatter: (src, edge_id) into dst-sorted order ----------------
__global__ void k_scatter(const int* __restrict__ src,
                          const int* __restrict__ dst)
{
    int e = blockIdx.x * blockDim.x + threadIdx.x;
    if (e >= NE) return;
    int d = dst[e];
    int idx = g_off[d] + g_pos[e];
    g_eidx[idx] = make_int2(src[e], e);
}

// ---------------- projection GEMM: tensor cores, 32 nodes/block ----------------
#define SROW 136   // padded smem row (halves): conflict-free fragment loads
__global__ void __launch_bounds__(128) k_gemm(
    const float* __restrict__ feat,
    const float* __restrict__ attn_l,
    const float* __restrict__ attn_r)
{
    __shared__ __half sA[32 * SROW];
    __shared__ float s_el[32][2][2], s_er[32][2][2];

    int t = threadIdx.x;
    int n0 = blockIdx.x * 32;
    int nrem = NN - n0;

    {
        const float4* fsrc = (const float4*)(feat + (size_t)n0 * IF);
#pragma unroll
        for (int k2 = 0; k2 < 8; k2++) {
            int g = t + k2 * 128;
            int node = g >> 5, c4 = g & 31;
            float4 v = (node < nrem) ? fsrc[g] : make_float4(0.f, 0.f, 0.f, 0.f);
            __half2 h0 = __floats2half2_rn(v.x, v.y);
            __half2 h1 = __floats2half2_rn(v.z, v.w);
            uint2 u;
            u.x = *(unsigned*)&h0;
            u.y = *(unsigned*)&h1;
            *(uint2*)&sA[node * SROW + c4 * 4] = u;
        }
    }
    __syncthreads();

    int w = t >> 5, lane = t & 31;
    int h = w >> 1, half64 = w & 1;
    int gid = lane >> 2, tig = lane & 3;
    int o_base = half64 * 64;

    float c[2][8][4];
#pragma unroll
    for (int tl = 0; tl < 2; tl++)
#pragma unroll
        for (int nt = 0; nt < 8; nt++) { c[tl][nt][0]=0.f; c[tl][nt][1]=0.f; c[tl][nt][2]=0.f; c[tl][nt][3]=0.f; }

#pragma unroll
    for (int ks = 0; ks < 8; ks++) {
        unsigned a[2][4];
#pragma unroll
        for (int tl = 0; tl < 2; tl++) {
            const __half* ar = sA + (tl * 16 + gid) * SROW + ks * 16 + 2 * tig;
            a[tl][0] = *(const unsigned*)(ar);
            a[tl][1] = *(const unsigned*)(ar + 8 * SROW);
            a[tl][2] = *(const unsigned*)(ar + 8);
            a[tl][3] = *(const unsigned*)(ar + 8 * SROW + 8);
        }
#pragma unroll
        for (int nt = 0; nt < 8; nt++) {
            uint2 b = __ldg(&g_Wf[(((h * 16 + half64 * 8 + nt) * 8) + ks) * 32 + lane]);
#pragma unroll
            for (int tl = 0; tl < 2; tl++) {
                asm volatile(
                    "mma.sync.aligned.m16n8k16.row.col.f32.f16.f16.f32 "
                    "{%0,%1,%2,%3}, {%4,%5,%6,%7}, {%8,%9}, {%0,%1,%2,%3};"
                    : "+f"(c[tl][nt][0]), "+f"(c[tl][nt][1]), "+f"(c[tl][nt][2]), "+f"(c[tl][nt][3])
                    : "r"(a[tl][0]), "r"(a[tl][1]), "r"(a[tl][2]), "r"(a[tl][3]),
                      "r"(b.x), "r"(b.y));
            }
        }
    }

#pragma unroll
    for (int tl = 0; tl < 2; tl++) {
        if (n0 + tl * 16 >= NN) break;
        float pl0 = 0.f, pl1 = 0.f, pr0 = 0.f, pr1 = 0.f;
#pragma unroll
        for (int nt = 0; nt < 8; nt++) {
            int o = o_base + nt * 8 + 2 * tig;
            float al0 = __ldg(&attn_l[h * 128 + o]), al1 = __ldg(&attn_l[h * 128 + o + 1]);
            float ar0 = __ldg(&attn_r[h * 128 + o]), ar1 = __ldg(&attn_r[h * 128 + o + 1]);
            pl0 += c[tl][nt][0] * al0 + c[tl][nt][1] * al1;
            pr0 += c[tl][nt][0] * ar0 + c[tl][nt][1] * ar1;
            pl1 += c[tl][nt][2] * al0 + c[tl][nt][3] * al1;
            pr1 += c[tl][nt][2] * ar0 + c[tl][nt][3] * ar1;
            __half2 lo = __floats2half2_rn(c[tl][nt][0], c[tl][nt][1]);
            __half2 hi = __floats2half2_rn(c[tl][nt][2], c[tl][nt][3]);
            int nb = n0 + tl * 16 + gid;
            ((unsigned*)g_fth)[(size_t)nb * 128 + h * 64 + (o >> 1)] = *(unsigned*)&lo;
            ((unsigned*)g_fth)[(size_t)(nb + 8) * 128 + h * 64 + (o >> 1)] = *(unsigned*)&hi;
        }
        pl0 += __shfl_xor_sync(0xffffffffu, pl0, 1); pl0 += __shfl_xor_sync(0xffffffffu, pl0, 2);
        pr0 += __shfl_xor_sync(0xffffffffu, pr0, 1); pr0 += __shfl_xor_sync(0xffffffffu, pr0, 2);
        pl1 += __shfl_xor_sync(0xffffffffu, pl1, 1); pl1 += __shfl_xor_sync(0xffffffffu, pl1, 2);
        pr1 += __shfl_xor_sync(0xffffffffu, pr1, 1); pr1 += __shfl_xor_sync(0xffffffffu, pr1, 2);
        if (tig == 0) {
            s_el[tl * 16 + gid][h][half64] = pl0;     s_er[tl * 16 + gid][h][half64] = pr0;
            s_el[tl * 16 + gid + 8][h][half64] = pl1; s_er[tl * 16 + gid + 8][h][half64] = pr1;
        }
    }
    __syncthreads();
    if (t < 64) {
        int node = t >> 1, hh = t & 1;
        if (n0 + node < NN) {
            g_el[(n0 + node) * 2 + hh] = s_el[node][hh][0] + s_el[node][hh][1];
            g_er[(n0 + node) * 2 + hh] = s_er[node][hh][0] + s_er[node][hh][1];
        }
    }
}

// ---------------- aggregation: warp per dst node, LDG.128 row gather ----------------
// Node row = 256 halves = 512B = 32 uint4. Lane l reads uint4 #l (8 channels):
// lanes 0-15 cover head 0, lanes 16-31 head 1.
#define AGG_WPB 8
__global__ void __launch_bounds__(AGG_WPB * 32) k_agg(
    const float* __restrict__ feat,
    const float* __restrict__ e_w,
    const float* __restrict__ attn_ew,
    float* __restrict__ out)
{
    __shared__ int   ssrc[AGG_WPB][32];
    __shared__ float sa0[AGG_WPB][32];
    __shared__ float sa1[AGG_WPB][32];

    int w = threadIdx.x >> 5, lane = threadIdx.x & 31;
    int d = blockIdx.x * AGG_WPB + w;
    if (d >= NN) return;

    int beg = g_off[d], end = g_off[d + 1];
    float2 erd = ((const float2*)g_er)[d];
    float w00 = __ldg(&attn_ew[0]), w01 = __ldg(&attn_ew[1]);
    float w10 = __ldg(&attn_ew[2]), w11 = __ldg(&attn_ew[3]);

    float acc[8];
#pragma unroll
    for (int q = 0; q < 8; q++) acc[q] = 0.0f;
    float dacc = 0.0f;
    int hsel = lane >> 4;   // 0: head0 lanes, 1: head1 lanes

    const uint4* fth4 = (const uint4*)g_fth;   // 32 uint4 per node row

    for (int base = beg; base < end; base += 32) {
        int n = min(32, end - base);
        if (lane < n) {
            int2 se = g_eidx[base + lane];
            int s = se.x, e = se.y;
            float2 ew = __ldg(&((const float2*)e_w)[e]);
            float2 a = __ldg(&((const float2*)g_el)[s]);
            float v0 = a.x + erd.x + ew.x * w00 + ew.y * w01;
            float v1 = a.y + erd.y + ew.x * w10 + ew.y * w11;
            v0 = v0 > 0.f ? v0 : 0.2f * v0;
            v1 = v1 > 0.f ? v1 : 0.2f * v1;
            ssrc[w][lane] = s;
            sa0[w][lane] = __expf(v0);
            sa1[w][lane] = __expf(v1);
        }
        __syncwarp();
        int j = 0;
        for (; j + 4 <= n; j += 4) {
            uint4 f[4];
            float a[4];
#pragma unroll
            for (int k = 0; k < 4; k++) {
                int s = ssrc[w][j + k];
                f[k] = __ldg(&fth4[(size_t)s * 32 + lane]);
                a[k] = hsel ? sa1[w][j + k] : sa0[w][j + k];
            }
#pragma unroll
            for (int k = 0; k < 4; k++) {
                const __half2* hp = (const __half2*)&f[k];
#pragma unroll
                for (int q = 0; q < 4; q++) {
                    float2 v = __half22float2(hp[q]);
                    acc[2 * q + 0] += v.x * a[k];
                    acc[2 * q + 1] += v.y * a[k];
                }
                dacc += a[k];
            }
        }
        for (; j < n; j++) {
            int s = ssrc[w][j];
            uint4 f = __ldg(&fth4[(size_t)s * 32 + lane]);
            float a = hsel ? sa1[w][j] : sa0[w][j];
            const __half2* hp = (const __half2*)&f;
#pragma unroll
            for (int q = 0; q < 4; q++) {
                float2 v = __half22float2(hp[q]);
                acc[2 * q + 0] += v.x * a;
                acc[2 * q + 1] += v.y * a;
            }
            dacc += a;
        }
        __syncwarp();
    }

    float inv = dacc > 0.f ? 1.0f / dacc : 0.0f;
    int o8 = (lane & 15) * 8;   // channel base within head
    const float4* fr = (const float4*)(feat + (size_t)d * 128 + o8);
    float4 r0 = __ldg(&fr[0]);
    float4 r1 = __ldg(&fr[1]);
    float rr[8] = {r0.x, r0.y, r0.z, r0.w, r1.x, r1.y, r1.z, r1.w};
#pragma unroll
    for (int q = 0; q < 8; q++) {
        float r = acc[q] * inv + rr[q];
        rr[q] = r > 0.f ? r : (__expf(r) - 1.0f);
    }
    float4* op = (float4*)(out + (size_t)d * 256 + hsel * 128 + o8);
    op[0] = make_float4(rr[0], rr[1], rr[2], rr[3]);
    op[1] = make_float4(rr[4], rr[5], rr[6], rr[7]);
}

// ---------------- launcher: CSR build fully overlapped with GEMM ----------------
extern "C" void kernel_launch(void* const* d_in, const int* in_sizes, int n_in,
                              void* d_out, int out_size)
{
    const float* feat    = (const float*)d_in[0];
    const float* e_w     = (const float*)d_in[1];
    const int*   src     = (const int*)  d_in[2];
    const int*   dst     = (const int*)  d_in[3];
    const float* W       = (const float*)d_in[4];
    const float* attn_l  = (const float*)d_in[5];
    const float* attn_r  = (const float*)d_in[6];
    const float* attn_ew = (const float*)d_in[7];
    float* out = (float*)d_out;

    cudaStream_t s2;
    cudaStreamCreate(&s2);
    cudaEvent_t evFork, evJoin;
    cudaEventCreateWithFlags(&evFork, cudaEventDisableTiming);
    cudaEventCreateWithFlags(&evJoin, cudaEventDisableTiming);

    cudaEventRecord(evFork, 0);

    // side stream: zero + full CSR build (independent of W/feat)
    cudaStreamWaitEvent(s2, evFork, 0);
    k_zero<<<(NN + 255) / 256, 256, 0, s2>>>();
    k_hist<<<(NE / 4 + 255) / 256, 256, 0, s2>>>(dst);
    k_scan<<<SCAN_NBLK, 1024, 0, s2>>>();
    k_scatter<<<(NE + 255) / 256, 256, 0, s2>>>(src, dst);
    cudaEventRecord(evJoin, s2);

    // main stream: W pack + projection GEMM
    k_setup<<<(HEADS * 16 * 8 * 32 + 255) / 256, 256>>>(W);
    k_gemm<<<(NN + 31) / 32, 128>>>(feat, attn_l, attn_r);

    // join, then fused softmax+aggregation
    cudaStreamWaitEvent(0, evJoin, 0);
    k_agg<<<(NN + AGG_WPB - 1) / AGG_WPB, AGG_WPB * 32>>>(feat, e_w, attn_ew, out);
}